// round 1
// baseline (speedup 1.0000x reference)
#include <cuda_runtime.h>

namespace {

constexpr int H  = 128;
constexpr int W  = 128;
constexpr int OH = 64;
constexpr int OW = 64;
constexpr int NT = 256;   // threads per block
constexpr int TAPS = 4;   // provably sufficient: window width 2*support <= 4

struct Smem {
    float img[H * W];       // 64 KB  input image
    float tmp[OH * W];      // 32 KB  row-resized intermediate
    float wh[OH][TAPS];     // row weights
    float ww[OW][TAPS];     // col weights
    int   jr[OH];           // row tap base index
    int   jc[OW];           // col tap base index
    float red[32];          // reduction scratch
    float thr;
    float lo_r, hi_r, lo_c, hi_c;
};

__device__ __forceinline__ float warpRedMax(float v) {
    #pragma unroll
    for (int s = 16; s > 0; s >>= 1) v = fmaxf(v, __shfl_xor_sync(0xffffffffu, v, s));
    return v;
}
__device__ __forceinline__ float warpRedMin(float v) {
    #pragma unroll
    for (int s = 16; s > 0; s >>= 1) v = fminf(v, __shfl_xor_sync(0xffffffffu, v, s));
    return v;
}

__global__ __launch_bounds__(NT) void smartpool_kernel(const float* __restrict__ x,
                                                       float* __restrict__ out) {
    extern __shared__ unsigned char smem_raw[];
    Smem& s = *reinterpret_cast<Smem*>(smem_raw);

    const int tid  = threadIdx.x;
    const int wid  = tid >> 5;
    const int lane = tid & 31;
    const float* xb = x + (size_t)blockIdx.x * (H * W);

    // ---- Pass 1: load image to smem (float4, coalesced) + block max ----
    float lmax = -3.0e38f;
    const float4* x4  = reinterpret_cast<const float4*>(xb);
    float4*       im4 = reinterpret_cast<float4*>(s.img);
    #pragma unroll
    for (int i = tid; i < (H * W) / 4; i += NT) {
        float4 v = x4[i];
        im4[i] = v;
        lmax = fmaxf(lmax, fmaxf(fmaxf(v.x, v.y), fmaxf(v.z, v.w)));
    }
    lmax = warpRedMax(lmax);
    if (lane == 0) s.red[wid] = lmax;
    __syncthreads();
    if (tid == 0) {
        float m = s.red[0];
        #pragma unroll
        for (int i = 1; i < NT / 32; i++) m = fmaxf(m, s.red[i]);
        s.thr = 0.1f * m;               // RATIO * max, fp32, same rounding as ref
    }
    __syncthreads();
    const float thr = s.thr;

    // ---- Pass 2: bbox reductions (faithful to reference's +-1e5 quirk) ----
    float rmin = 3.0e38f, rmax = -3.0e38f, cmin = 3.0e38f, cmax = -3.0e38f;
    #pragma unroll 4
    for (int k = 0; k < (H * W) / NT; k++) {
        int idx = tid + k * NT;
        float v = s.img[idx];
        int h = idx >> 7, w = idx & 127;
        float tb = (v >= thr) ? 1.0f : 0.0f;
        float fh = tb * (float)h;
        float fw = tb * (float)w;
        rmin = fminf(rmin, (h == 0) ?  1e5f : fh);
        rmax = fmaxf(rmax, (h == 0) ? -1e5f : fh);
        cmin = fminf(cmin, (w == 0) ?  1e5f : fw);
        cmax = fmaxf(cmax, (w == 0) ? -1e5f : fw);
    }
    rmin = warpRedMin(rmin); rmax = warpRedMax(rmax);
    cmin = warpRedMin(cmin); cmax = warpRedMax(cmax);
    if (lane == 0) {
        s.red[wid]      = rmin;
        s.red[8 + wid]  = rmax;
        s.red[16 + wid] = cmin;
        s.red[24 + wid] = cmax;
    }
    __syncthreads();
    if (tid == 0) {
        float a = s.red[0], b = s.red[8], c = s.red[16], d = s.red[24];
        #pragma unroll
        for (int i = 1; i < 8; i++) {
            a = fminf(a, s.red[i]);      b = fmaxf(b, s.red[8 + i]);
            c = fminf(c, s.red[16 + i]); d = fmaxf(d, s.red[24 + i]);
        }
        s.lo_r = a; s.hi_r = b; s.lo_c = c; s.hi_c = d;
    }
    __syncthreads();

    // ---- Weights: thread o in [0,64) -> row weights, [64,128) -> col weights.
    // All window math is exact in fp32 (small integers / L/64 / half-integers),
    // so ceil(base - support) + 4 taps covers every nonzero weight exactly.
    if (tid < OH + OW) {
        const bool isRow = tid < OH;
        const int  o  = isRow ? tid : tid - OH;
        const float lo = isRow ? s.lo_r : s.lo_c;
        const float hi = isRow ? s.hi_r : s.hi_c;
        const float L       = hi - lo + 1.0f;
        const float scale   = L / 64.0f;
        const float support = fmaxf(scale, 1.0f);
        const float center  = scale * ((float)o + 0.5f);
        const float base    = (lo - 0.5f) + center;
        float a0 = fminf(fmaxf(base - support, -8.0f), 160.0f);  // safety clamp
        int j0 = (int)ceilf(a0);
        float wv[TAPS];
        float ssum = 0.0f;
        #pragma unroll
        for (int a = 0; a < TAPS; a++) {
            float jf  = (float)(j0 + a);
            float pos = (jf - lo) + 0.5f;
            float t   = (pos - center) / support;
            float wt  = fmaxf(0.0f, 1.0f - fabsf(t));
            if (!(jf >= lo && jf <= hi)) wt = 0.0f;    // valid mask
            wv[a] = wt;
            ssum += wt;
        }
        float denom = fmaxf(ssum, 1e-12f);
        if (isRow) {
            s.jr[o] = j0;
            #pragma unroll
            for (int a = 0; a < TAPS; a++) s.wh[o][a] = wv[a] / denom;
        } else {
            s.jc[o] = j0;
            #pragma unroll
            for (int a = 0; a < TAPS; a++) s.ww[o][a] = wv[a] / denom;
        }
    }
    __syncthreads();

    // ---- Row resize: tmp[o][w] = sum_a wh[o][a] * img[j0+a][w] ----
    #pragma unroll 4
    for (int i = tid; i < OH * W; i += NT) {
        int o  = i >> 7;
        int wc = i & 127;
        int j0 = s.jr[o];
        const float* wrow = s.wh[o];
        float acc = 0.0f;
        #pragma unroll
        for (int a = 0; a < TAPS; a++) {
            int j = min(max(j0 + a, 0), H - 1);   // clamp; OOB taps have weight 0
            acc = fmaf(wrow[a], s.img[j * W + wc], acc);
        }
        s.tmp[i] = acc;
    }
    __syncthreads();

    // ---- Col resize + writeout: out[o][p] = sum_b ww[p][b] * tmp[o][k0+b] ----
    float* ob = out + (size_t)blockIdx.x * (OH * OW);
    #pragma unroll 4
    for (int i = tid; i < OH * OW; i += NT) {
        int o  = i >> 6;
        int p  = i & 63;
        int k0 = s.jc[p];
        const float* wcol = s.ww[p];
        float acc = 0.0f;
        #pragma unroll
        for (int b = 0; b < TAPS; b++) {
            int k = min(max(k0 + b, 0), W - 1);
            acc = fmaf(wcol[b], s.tmp[o * W + k], acc);
        }
        ob[i] = acc;
    }
}

} // anonymous namespace

extern "C" void kernel_launch(void* const* d_in, const int* in_sizes, int n_in,
                              void* d_out, int out_size) {
    const float* x = (const float*)d_in[0];
    float* out = (float*)d_out;
    const int nimg = in_sizes[0] / (H * W);   // N*C = 4096
    cudaFuncSetAttribute(smartpool_kernel,
                         cudaFuncAttributeMaxDynamicSharedMemorySize,
                         (int)sizeof(Smem));
    smartpool_kernel<<<nimg, NT, sizeof(Smem)>>>(x, out);
}

// round 6
// speedup vs baseline: 1.1378x; 1.1378x over previous
#include <cuda_runtime.h>

namespace {

constexpr int H  = 128;
constexpr int W  = 128;
constexpr int OH = 64;
constexpr int OW = 64;
constexpr int NT = 256;       // threads per block
constexpr int TAPS = 4;       // window width 2*support <= 4 (exact in fp32)
constexpr int STRIPE = 8;     // tmp rows per stripe
constexpr int NSTRIPES = OH / STRIPE;

struct Smem {
    float img[H * W];            // 64 KB input image
    float tmp[STRIPE * W];       // 4 KB  row-resized stripe
    float wh[OH][TAPS];          // row weights
    float ww[OW][TAPS];          // col weights
    int   jr[OH];                // row tap base
    int   jc[OW];                // col tap base
    float red[32];
    float thr;
    float lo_r, hi_r, lo_c, hi_c;
};

__device__ __forceinline__ float warpRedMax(float v) {
    #pragma unroll
    for (int s = 16; s > 0; s >>= 1) v = fmaxf(v, __shfl_xor_sync(0xffffffffu, v, s));
    return v;
}
__device__ __forceinline__ float warpRedMin(float v) {
    #pragma unroll
    for (int s = 16; s > 0; s >>= 1) v = fminf(v, __shfl_xor_sync(0xffffffffu, v, s));
    return v;
}

__global__ __launch_bounds__(NT, 3) void smartpool_kernel(const float* __restrict__ x,
                                                          float* __restrict__ out) {
    extern __shared__ unsigned char smem_raw[];
    Smem& s = *reinterpret_cast<Smem*>(smem_raw);

    const int tid  = threadIdx.x;
    const int wid  = tid >> 5;
    const int lane = tid & 31;
    const float* xb = x + (size_t)blockIdx.x * (H * W);

    // ---- Pass 1: global -> smem (float4) + block max ----
    float lmax = -3.0e38f;
    const float4* x4  = reinterpret_cast<const float4*>(xb);
    float4*       im4 = reinterpret_cast<float4*>(s.img);
    #pragma unroll
    for (int k = 0; k < (H * W) / 4 / NT; k++) {
        float4 v = x4[tid + k * NT];
        im4[tid + k * NT] = v;
        lmax = fmaxf(lmax, fmaxf(fmaxf(v.x, v.y), fmaxf(v.z, v.w)));
    }
    lmax = warpRedMax(lmax);
    if (lane == 0) s.red[wid] = lmax;
    __syncthreads();
    if (tid == 0) {
        float m = s.red[0];
        #pragma unroll
        for (int i = 1; i < NT / 32; i++) m = fmaxf(m, s.red[i]);
        s.thr = 0.1f * m;
    }
    __syncthreads();
    const float thr = s.thr;

    // ---- Pass 2: bbox reductions, vectorized LDS.128 ----
    // Reference candidates: the h==0 row contributes exactly {+1e5,-1e5} to the
    // row stats; the w==0 col contributes exactly {+1e5,-1e5} to the col stats.
    // All h>0 (w>0) candidates lie in [0,127], so initializing rmin=+1e5,
    // rmax=-1e5 (cmin,cmax likewise) and skipping h==0 / w==0 updates is exact.
    float rmin = 1e5f, rmax = -1e5f, cmin = 1e5f, cmax = -1e5f;
    #pragma unroll
    for (int k = 0; k < (H * W) / 4 / NT; k++) {
        int i = tid + k * NT;                 // float4 index
        float4 v = im4[i];
        int h = i >> 5;                       // row (constant per float4)
        int wbase = (i & 31) << 2;            // first col of this float4
        float fh = (float)h;
        float t0 = (v.x >= thr) ? 1.0f : 0.0f;
        float t1 = (v.y >= thr) ? 1.0f : 0.0f;
        float t2 = (v.z >= thr) ? 1.0f : 0.0f;
        float t3 = (v.w >= thr) ? 1.0f : 0.0f;
        if (h != 0) {
            float a = fminf(fminf(t0, t1), fminf(t2, t3)) * fh;  // min of tb*h
            float b = fmaxf(fmaxf(t0, t1), fmaxf(t2, t3)) * fh;  // max of tb*h
            rmin = fminf(rmin, a);
            rmax = fmaxf(rmax, b);
        }
        float w0 = (float)wbase;
        float c1v = t1 * (w0 + 1.0f), c2v = t2 * (w0 + 2.0f), c3v = t3 * (w0 + 3.0f);
        float mn = fminf(c1v, fminf(c2v, c3v));
        float mx = fmaxf(c1v, fmaxf(c2v, c3v));
        if (wbase != 0) {                     // include the c==0 element
            float c0v = t0 * w0;
            mn = fminf(mn, c0v);
            mx = fmaxf(mx, c0v);
        }
        cmin = fminf(cmin, mn);
        cmax = fmaxf(cmax, mx);
    }
    rmin = warpRedMin(rmin); rmax = warpRedMax(rmax);
    cmin = warpRedMin(cmin); cmax = warpRedMax(cmax);
    if (lane == 0) {
        s.red[wid]      = rmin;
        s.red[8 + wid]  = rmax;
        s.red[16 + wid] = cmin;
        s.red[24 + wid] = cmax;
    }
    __syncthreads();
    if (tid == 0) {
        float a = s.red[0], b = s.red[8], c = s.red[16], d = s.red[24];
        #pragma unroll
        for (int i = 1; i < 8; i++) {
            a = fminf(a, s.red[i]);      b = fmaxf(b, s.red[8 + i]);
            c = fminf(c, s.red[16 + i]); d = fmaxf(d, s.red[24 + i]);
        }
        s.lo_r = a; s.hi_r = b; s.lo_c = c; s.hi_c = d;
    }
    __syncthreads();

    // ---- Weights (threads 0..127): exact fp32 window math, 4 taps suffice ----
    if (tid < OH + OW) {
        const bool isRow = tid < OH;
        const int  o  = isRow ? tid : tid - OH;
        const float lo = isRow ? s.lo_r : s.lo_c;
        const float hi = isRow ? s.hi_r : s.hi_c;
        const float L       = hi - lo + 1.0f;
        const float scale   = L / 64.0f;
        const float support = fmaxf(scale, 1.0f);
        const float center  = scale * ((float)o + 0.5f);
        const float base    = (lo - 0.5f) + center;
        float a0 = fminf(fmaxf(base - support, -8.0f), 160.0f);
        int j0 = (int)ceilf(a0);
        float wv[TAPS];
        float ssum = 0.0f;
        #pragma unroll
        for (int a = 0; a < TAPS; a++) {
            float jf  = (float)(j0 + a);
            float pos = (jf - lo) + 0.5f;
            float t   = (pos - center) / support;
            float wt  = fmaxf(0.0f, 1.0f - fabsf(t));
            if (!(jf >= lo && jf <= hi)) wt = 0.0f;
            wv[a] = wt;
            ssum += wt;
        }
        float denom = fmaxf(ssum, 1e-12f);
        if (isRow) {
            s.jr[o] = j0;
            #pragma unroll
            for (int a = 0; a < TAPS; a++) s.wh[o][a] = wv[a] / denom;
        } else {
            s.jc[o] = j0;
            #pragma unroll
            for (int a = 0; a < TAPS; a++) s.ww[o][a] = wv[a] / denom;
        }
    }
    __syncthreads();

    // ---- Striped row+col resize: 8 output rows per stripe ----
    float* ob = out + (size_t)blockIdx.x * (OH * OW);
    float4* tmp4 = reinterpret_cast<float4*>(s.tmp);

    #pragma unroll 1
    for (int st = 0; st < NSTRIPES; st++) {
        // Row pass: one float4 of one tmp row per thread (warp = one row).
        {
            int o  = st * STRIPE + (tid >> 5);     // output row
            int wq = tid & 31;                     // float4 col index
            int j0 = s.jr[o];
            const float* wrow = s.wh[o];
            float4 acc = make_float4(0.f, 0.f, 0.f, 0.f);
            #pragma unroll
            for (int a = 0; a < TAPS; a++) {
                int j = min(max(j0 + a, 0), H - 1);   // OOB taps have weight 0
                float4 v = im4[j * (W / 4) + wq];
                float wt = wrow[a];
                acc.x = fmaf(wt, v.x, acc.x);
                acc.y = fmaf(wt, v.y, acc.y);
                acc.z = fmaf(wt, v.z, acc.z);
                acc.w = fmaf(wt, v.w, acc.w);
            }
            tmp4[(tid >> 5) * (W / 4) + wq] = acc;
        }
        __syncthreads();

        // Col pass: STRIPE*OW = 512 outputs, 2 per thread; coalesced STG.
        #pragma unroll
        for (int it = 0; it < (STRIPE * OW) / NT; it++) {
            int i = tid + it * NT;
            int ol = i >> 6;                       // local row in stripe
            int p  = i & 63;
            int k0 = s.jc[p];
            const float* wcol = s.ww[p];
            const float* trow = s.tmp + ol * W;
            float acc = 0.0f;
            #pragma unroll
            for (int b = 0; b < TAPS; b++) {
                int kk = min(max(k0 + b, 0), W - 1);
                acc = fmaf(wcol[b], trow[kk], acc);
            }
            ob[(st * STRIPE + ol) * OW + p] = acc;
        }
        __syncthreads();
    }
}

} // anonymous namespace

extern "C" void kernel_launch(void* const* d_in, const int* in_sizes, int n_in,
                              void* d_out, int out_size) {
    const float* x = (const float*)d_in[0];
    float* out = (float*)d_out;
    const int nimg = in_sizes[0] / (H * W);   // N*C = 4096
    cudaFuncSetAttribute(smartpool_kernel,
                         cudaFuncAttributeMaxDynamicSharedMemorySize,
                         (int)sizeof(Smem));
    smartpool_kernel<<<nimg, NT, sizeof(Smem)>>>(x, out);
}

// round 7
// speedup vs baseline: 1.2517x; 1.1002x over previous
#include <cuda_runtime.h>

namespace {

constexpr int H  = 128;
constexpr int W  = 128;
constexpr int OH = 64;
constexpr int OW = 64;
constexpr int NT = 256;       // threads per block
constexpr int TAPS = 4;       // window width 2*support <= 4 (exact in fp32)
constexpr int STRIPE = 8;     // tmp rows per stripe
constexpr int NSTRIPES = OH / STRIPE;

struct Smem {
    float img[H * W];            // 64 KB input image
    float tmp[STRIPE * W];       // 4 KB: col-reduce scratch early, tmp stripe later
    float rowmax[H];             // per-row max
    float wh[OH][TAPS];          // row weights
    float ww[OW][TAPS];          // col weights
    int   jr[OH];                // row tap base
    int   jc[OW];                // col tap base
    float red[32];
    float thr;
    float lo_r, hi_r, lo_c, hi_c;
};

__device__ __forceinline__ float warpRedMax(float v) {
    #pragma unroll
    for (int s = 16; s > 0; s >>= 1) v = fmaxf(v, __shfl_xor_sync(0xffffffffu, v, s));
    return v;
}
__device__ __forceinline__ float warpRedMin(float v) {
    #pragma unroll
    for (int s = 16; s > 0; s >>= 1) v = fminf(v, __shfl_xor_sync(0xffffffffu, v, s));
    return v;
}

__global__ __launch_bounds__(NT, 3) void smartpool_kernel(const float* __restrict__ x,
                                                          float* __restrict__ out) {
    extern __shared__ unsigned char smem_raw[];
    Smem& s = *reinterpret_cast<Smem*>(smem_raw);

    const int tid  = threadIdx.x;
    const int wid  = tid >> 5;
    const int lane = tid & 31;
    const float* xb = x + (size_t)blockIdx.x * (H * W);

    // colpart aliases s.tmp (tmp unused until the resize, after stats are done)
    float (*colpart)[W] = reinterpret_cast<float (*)[W]>(s.tmp);

    // ---- Pass 1: global -> smem + ALL statistics fused under the load ----
    // Thread layout: float4 index i = tid + 256k  ->  row = wid + 8k, lane
    // covers cols [4*lane, 4*lane+3].  So per k, warp `wid` reads exactly one
    // full row, and each lane owns a fixed set of 4 columns across its rows.
    //
    // Bbox equivalence (exact): reference candidates are table*idx plus +-1e5
    // sentinels on row/col 0.  Since table*idx in {0, idx} with idx in [0,127]:
    //   x_min = 1 if ALL elements in rows 1..127 are active (>= thr) else 0
    //   x_max = max{ h>=1 : any element of row h >= thr }, else 0
    //   (y_* symmetric over columns, all rows).
    // "any >= thr" <=> rowmax >= thr; "all >= thr" <=> regionmin >= thr.
    float gmax   = -3.0e38f;
    float4 cmax4 = make_float4(-3.0e38f, -3.0e38f, -3.0e38f, -3.0e38f);
    float minR   = 3.0e38f;    // min over rows 1..127 (all cols)
    float minC   = 3.0e38f;    // min over cols 1..127 (all rows)

    const float4* x4  = reinterpret_cast<const float4*>(xb);
    float4*       im4 = reinterpret_cast<float4*>(s.img);
    #pragma unroll
    for (int k = 0; k < 16; k++) {
        float4 v = x4[tid + k * NT];
        im4[tid + k * NT] = v;
        float m4 = fmaxf(fmaxf(v.x, v.y), fmaxf(v.z, v.w));
        float n4 = fminf(fminf(v.x, v.y), fminf(v.z, v.w));
        gmax = fmaxf(gmax, m4);
        cmax4.x = fmaxf(cmax4.x, v.x);
        cmax4.y = fmaxf(cmax4.y, v.y);
        cmax4.z = fmaxf(cmax4.z, v.z);
        cmax4.w = fmaxf(cmax4.w, v.w);
        // row index = wid + 8k; row 0 occurs only for wid==0,k==0
        if (k > 0 || wid != 0) minR = fminf(minR, n4);
        float nc = (lane == 0) ? fminf(fminf(v.y, v.z), v.w) : n4;  // drop col 0
        minC = fminf(minC, nc);
        float rm = warpRedMax(m4);                 // max of this full row
        if (lane == 0) s.rowmax[wid + 8 * k] = rm;
    }
    // column partials: colpart[wid][4*lane .. 4*lane+3]
    reinterpret_cast<float4*>(colpart[wid])[lane] = cmax4;

    // block-reduce gmax / minR / minC
    gmax = warpRedMax(gmax);
    minR = warpRedMin(minR);
    minC = warpRedMin(minC);
    if (lane == 0) { s.red[wid] = gmax; s.red[8 + wid] = minR; s.red[16 + wid] = minC; }
    __syncthreads();
    if (tid == 0) {
        float g = s.red[0], mr = s.red[8], mc = s.red[16];
        #pragma unroll
        for (int i = 1; i < 8; i++) {
            g  = fmaxf(g,  s.red[i]);
            mr = fminf(mr, s.red[8 + i]);
            mc = fminf(mc, s.red[16 + i]);
        }
        float thr = 0.1f * g;
        s.thr  = thr;
        s.lo_r = (mr >= thr) ? 1.0f : 0.0f;
        s.lo_c = (mc >= thr) ? 1.0f : 0.0f;
    }
    __syncthreads();
    const float thr = s.thr;

    // hi_r / hi_c: threads 0..127 scan rowmax / reduced colmax
    if (tid < 128) {
        float rm = s.rowmax[tid];
        float cm = colpart[0][tid];
        #pragma unroll
        for (int w = 1; w < 8; w++) cm = fmaxf(cm, colpart[w][tid]);
        float candR = (tid >= 1 && rm >= thr) ? (float)tid : 0.0f;
        float candC = (tid >= 1 && cm >= thr) ? (float)tid : 0.0f;
        candR = warpRedMax(candR);
        candC = warpRedMax(candC);
        if (lane == 0) { s.red[wid] = candR; s.red[8 + wid] = candC; }
    }
    __syncthreads();
    if (tid == 0) {
        float hr = s.red[0], hc = s.red[8];
        #pragma unroll
        for (int i = 1; i < 4; i++) { hr = fmaxf(hr, s.red[i]); hc = fmaxf(hc, s.red[8 + i]); }
        s.hi_r = hr; s.hi_c = hc;
    }
    __syncthreads();

    // ---- Weights (threads 0..127): exact fp32 window math, 4 taps suffice ----
    if (tid < OH + OW) {
        const bool isRow = tid < OH;
        const int  o  = isRow ? tid : tid - OH;
        const float lo = isRow ? s.lo_r : s.lo_c;
        const float hi = isRow ? s.hi_r : s.hi_c;
        const float L       = hi - lo + 1.0f;
        const float scale   = L / 64.0f;
        const float support = fmaxf(scale, 1.0f);
        const float center  = scale * ((float)o + 0.5f);
        const float base    = (lo - 0.5f) + center;
        float a0 = fminf(fmaxf(base - support, -8.0f), 160.0f);
        int j0 = (int)ceilf(a0);
        float wv[TAPS];
        float ssum = 0.0f;
        #pragma unroll
        for (int a = 0; a < TAPS; a++) {
            float jf  = (float)(j0 + a);
            float pos = (jf - lo) + 0.5f;
            float t   = (pos - center) / support;
            float wt  = fmaxf(0.0f, 1.0f - fabsf(t));
            if (!(jf >= lo && jf <= hi)) wt = 0.0f;
            wv[a] = wt;
            ssum += wt;
        }
        float denom = fmaxf(ssum, 1e-12f);
        if (isRow) {
            s.jr[o] = j0;
            #pragma unroll
            for (int a = 0; a < TAPS; a++) s.wh[o][a] = wv[a] / denom;
        } else {
            s.jc[o] = j0;
            #pragma unroll
            for (int a = 0; a < TAPS; a++) s.ww[o][a] = wv[a] / denom;
        }
    }
    __syncthreads();   // also fences colpart (tmp) reuse below

    // ---- Striped row+col resize: 8 output rows per stripe ----
    float* ob = out + (size_t)blockIdx.x * (OH * OW);
    float4* tmp4 = reinterpret_cast<float4*>(s.tmp);

    #pragma unroll 1
    for (int st = 0; st < NSTRIPES; st++) {
        // Row pass: one float4 of one tmp row per thread (warp = one row).
        {
            int o  = st * STRIPE + wid;            // output row
            int wq = lane;                         // float4 col index
            int j0 = s.jr[o];
            const float* wrow = s.wh[o];
            float4 acc = make_float4(0.f, 0.f, 0.f, 0.f);
            #pragma unroll
            for (int a = 0; a < TAPS; a++) {
                int j = min(max(j0 + a, 0), H - 1);   // OOB taps have weight 0
                float4 v = im4[j * (W / 4) + wq];
                float wt = wrow[a];
                acc.x = fmaf(wt, v.x, acc.x);
                acc.y = fmaf(wt, v.y, acc.y);
                acc.z = fmaf(wt, v.z, acc.z);
                acc.w = fmaf(wt, v.w, acc.w);
            }
            tmp4[wid * (W / 4) + wq] = acc;
        }
        __syncthreads();

        // Col pass: STRIPE*OW = 512 outputs, 2 per thread; coalesced STG.
        #pragma unroll
        for (int it = 0; it < (STRIPE * OW) / NT; it++) {
            int i = tid + it * NT;
            int ol = i >> 6;                       // local row in stripe
            int p  = i & 63;
            int k0 = s.jc[p];
            const float* wcol = s.ww[p];
            const float* trow = s.tmp + ol * W;
            float acc = 0.0f;
            #pragma unroll
            for (int b = 0; b < TAPS; b++) {
                int kk = min(max(k0 + b, 0), W - 1);
                acc = fmaf(wcol[b], trow[kk], acc);
            }
            ob[(st * STRIPE + ol) * OW + p] = acc;
        }
        __syncthreads();
    }
}

} // anonymous namespace

extern "C" void kernel_launch(void* const* d_in, const int* in_sizes, int n_in,
                              void* d_out, int out_size) {
    const float* x = (const float*)d_in[0];
    float* out = (float*)d_out;
    const int nimg = in_sizes[0] / (H * W);   // N*C = 4096
    cudaFuncSetAttribute(smartpool_kernel,
                         cudaFuncAttributeMaxDynamicSharedMemorySize,
                         (int)sizeof(Smem));
    smartpool_kernel<<<nimg, NT, sizeof(Smem)>>>(x, out);
}

// round 9
// speedup vs baseline: 1.6159x; 1.2909x over previous
#include <cuda_runtime.h>

namespace {

constexpr int H  = 128;
constexpr int W  = 128;
constexpr int OH = 64;
constexpr int OW = 64;
constexpr int NT = 256;       // threads per block
constexpr int TAPS = 4;       // window width 2*support <= 4 (exact in fp32)
constexpr int STRIPE = 8;     // tmp rows per stripe (generic path)
constexpr int NSTRIPES = OH / STRIPE;

// Full-bbox weights (exact): interior [1,3,3,1]/8; edges [3,3,1]/7 pattern.
constexpr float WI0 = 0.125f;          // 1/8
constexpr float WI1 = 0.375f;          // 3/8
constexpr float CE0 = 0.75f / 1.75f;   // 3/7, correctly rounded like ref's w/s
constexpr float CE1 = 0.25f / 1.75f;   // 1/7

struct Smem {
    float img[H * W];            // 64 KB input image
    float tmp[STRIPE * W];       // 4 KB: col-reduce scratch early, tmp stripe later
    float rowmax[H];             // per-row max
    float wh[OH][TAPS];          // row weights (generic path)
    float ww[OW][TAPS];          // col weights (generic path)
    int   jr[OH];                // row tap base (generic)
    int   jc[OW];                // col tap base (generic)
    float red[32];
    float thr;
    float lo_r, hi_r, lo_c, hi_c;
};

__device__ __forceinline__ float warpRedMax(float v) {
    #pragma unroll
    for (int s = 16; s > 0; s >>= 1) v = fmaxf(v, __shfl_xor_sync(0xffffffffu, v, s));
    return v;
}
__device__ __forceinline__ float warpRedMin(float v) {
    #pragma unroll
    for (int s = 16; s > 0; s >>= 1) v = fminf(v, __shfl_xor_sync(0xffffffffu, v, s));
    return v;
}

__global__ __launch_bounds__(NT, 3) void smartpool_kernel(const float* __restrict__ x,
                                                          float* __restrict__ out) {
    extern __shared__ unsigned char smem_raw[];
    Smem& s = *reinterpret_cast<Smem*>(smem_raw);

    const int tid  = threadIdx.x;
    const int wid  = tid >> 5;
    const int lane = tid & 31;
    const float* xb = x + (size_t)blockIdx.x * (H * W);

    // colpart aliases s.tmp (tmp unused until the generic resize)
    float (*colpart)[W] = reinterpret_cast<float (*)[W]>(s.tmp);

    // ---- Pass 1: global -> smem + ALL statistics fused under the load ----
    // i = tid + 256k -> row = wid + 8k; lane covers cols [4*lane, 4*lane+3].
    // Bbox equivalence (exact):
    //   x_min = (min over rows 1..127 >= thr) ? 1 : 0
    //   x_max = max{ h>=1 : rowmax[h] >= thr }, else 0   (y_* symmetric)
    float gmax   = -3.0e38f;
    float4 cmax4 = make_float4(-3.0e38f, -3.0e38f, -3.0e38f, -3.0e38f);
    float minR   = 3.0e38f;    // min over rows 1..127 (all cols)
    float minC   = 3.0e38f;    // min over cols 1..127 (all rows)

    const float4* x4  = reinterpret_cast<const float4*>(xb);
    float4*       im4 = reinterpret_cast<float4*>(s.img);
    #pragma unroll
    for (int k = 0; k < 16; k++) {
        float4 v = x4[tid + k * NT];
        im4[tid + k * NT] = v;
        float m4 = fmaxf(fmaxf(v.x, v.y), fmaxf(v.z, v.w));
        float n4 = fminf(fminf(v.x, v.y), fminf(v.z, v.w));
        gmax = fmaxf(gmax, m4);
        cmax4.x = fmaxf(cmax4.x, v.x);
        cmax4.y = fmaxf(cmax4.y, v.y);
        cmax4.z = fmaxf(cmax4.z, v.z);
        cmax4.w = fmaxf(cmax4.w, v.w);
        if (k > 0 || wid != 0) minR = fminf(minR, n4);               // skip row 0
        float nc = (lane == 0) ? fminf(fminf(v.y, v.z), v.w) : n4;   // skip col 0
        minC = fminf(minC, nc);
        float rm = warpRedMax(m4);
        if (lane == 0) s.rowmax[wid + 8 * k] = rm;
    }
    reinterpret_cast<float4*>(colpart[wid])[lane] = cmax4;

    gmax = warpRedMax(gmax);
    minR = warpRedMin(minR);
    minC = warpRedMin(minC);
    if (lane == 0) { s.red[wid] = gmax; s.red[8 + wid] = minR; s.red[16 + wid] = minC; }
    __syncthreads();
    if (tid == 0) {
        float g = s.red[0], mr = s.red[8], mc = s.red[16];
        #pragma unroll
        for (int i = 1; i < 8; i++) {
            g  = fmaxf(g,  s.red[i]);
            mr = fminf(mr, s.red[8 + i]);
            mc = fminf(mc, s.red[16 + i]);
        }
        float thr = 0.1f * g;
        s.thr  = thr;
        s.lo_r = (mr >= thr) ? 1.0f : 0.0f;
        s.lo_c = (mc >= thr) ? 1.0f : 0.0f;
    }
    __syncthreads();
    const float thr = s.thr;

    if (tid < 128) {
        float rm = s.rowmax[tid];
        float cm = colpart[0][tid];
        #pragma unroll
        for (int w = 1; w < 8; w++) cm = fmaxf(cm, colpart[w][tid]);
        float candR = (tid >= 1 && rm >= thr) ? (float)tid : 0.0f;
        float candC = (tid >= 1 && cm >= thr) ? (float)tid : 0.0f;
        candR = warpRedMax(candR);
        candC = warpRedMax(candC);
        if (lane == 0) { s.red[wid] = candR; s.red[8 + wid] = candC; }
    }
    __syncthreads();
    if (tid == 0) {
        float hr = s.red[0], hc = s.red[8];
        #pragma unroll
        for (int i = 1; i < 4; i++) { hr = fmaxf(hr, s.red[i]); hc = fmaxf(hc, s.red[8 + i]); }
        s.hi_r = hr; s.hi_c = hc;
    }
    __syncthreads();

    const bool fastpath = (s.lo_r == 0.0f) && (s.hi_r == 127.0f) &&
                          (s.lo_c == 0.0f) && (s.hi_c == 127.0f);
    float* ob = out + (size_t)blockIdx.x * (OH * OW);

    if (fastpath) {
        // ===== Fast path: fixed [1,3,3,1]/8 stencil (edges [3,3,1]/7). =====
        // Warp computes output-row PAIR (o=2p, 2p+1): 6 smem row reads, column
        // resize in registers via shuffles, direct coalesced gmem store.
        // No barriers.
        // Column weights per lane (p0 = 2*lane, p1 = 2*lane+1), fixed:
        const float w0 = (lane == 0)  ? 0.0f : WI0;   // col 4l-1 (via shfl_up)
        const float w1 = (lane == 0)  ? CE0  : WI1;   // col 4l
        const float w2 = (lane == 0)  ? CE0  : WI1;   // col 4l+1
        const float w3 = (lane == 0)  ? CE1  : WI0;   // col 4l+2
        const float u0 = (lane == 31) ? CE1  : WI0;   // col 4l+1
        const float u1 = (lane == 31) ? CE0  : WI1;   // col 4l+2
        const float u2 = (lane == 31) ? CE0  : WI1;   // col 4l+3
        const float u3 = (lane == 31) ? 0.0f : WI0;   // col 4l+4 (via shfl_down)

        #pragma unroll
        for (int t = 0; t < 4; t++) {
            const int p  = wid + 8 * t;           // pair index, 0..31
            const int r0 = 4 * p - 1;             // first tap row (slot 0)
            // Row weights for outA (o=2p): slots 0..3; outB (o=2p+1): slots 2..5
            const float a0 = (p == 0)  ? 0.0f : WI0;
            const float a1 = (p == 0)  ? CE0  : WI1;
            const float a2 = (p == 0)  ? CE0  : WI1;
            const float a3 = (p == 0)  ? CE1  : WI0;
            const float b0 = (p == 31) ? CE1  : WI0;
            const float b1 = (p == 31) ? CE0  : WI1;
            const float b2 = (p == 31) ? CE0  : WI1;
            const float b3 = (p == 31) ? 0.0f : WI0;

            float4 accA = make_float4(0.f, 0.f, 0.f, 0.f);
            float4 accB = make_float4(0.f, 0.f, 0.f, 0.f);
            #pragma unroll
            for (int sl = 0; sl < 6; sl++) {
                int rr = min(max(r0 + sl, 0), H - 1);   // clamped rows have w=0
                float4 v = im4[rr * (W / 4) + lane];
                float wa = (sl == 0) ? a0 : (sl == 1) ? a1 : (sl == 2) ? a2
                         : (sl == 3) ? a3 : 0.0f;
                float wb = (sl == 2) ? b0 : (sl == 3) ? b1 : (sl == 4) ? b2
                         : (sl == 5) ? b3 : 0.0f;
                if (sl < 4) {
                    accA.x = fmaf(wa, v.x, accA.x);
                    accA.y = fmaf(wa, v.y, accA.y);
                    accA.z = fmaf(wa, v.z, accA.z);
                    accA.w = fmaf(wa, v.w, accA.w);
                }
                if (sl >= 2) {
                    accB.x = fmaf(wb, v.x, accB.x);
                    accB.y = fmaf(wb, v.y, accB.y);
                    accB.z = fmaf(wb, v.z, accB.z);
                    accB.w = fmaf(wb, v.w, accB.w);
                }
            }
            // Column resize in registers (2 outputs per lane per row).
            {
                float lA = __shfl_up_sync(0xffffffffu, accA.w, 1);   // col 4l-1
                float rA = __shfl_down_sync(0xffffffffu, accA.x, 1); // col 4l+4
                float o0 = fmaf(w0, lA, fmaf(w1, accA.x, fmaf(w2, accA.y, w3 * accA.z)));
                float o1 = fmaf(u0, accA.y, fmaf(u1, accA.z, fmaf(u2, accA.w, u3 * rA)));
                reinterpret_cast<float2*>(ob + (2 * p) * OW)[lane] = make_float2(o0, o1);
            }
            {
                float lB = __shfl_up_sync(0xffffffffu, accB.w, 1);
                float rB = __shfl_down_sync(0xffffffffu, accB.x, 1);
                float o0 = fmaf(w0, lB, fmaf(w1, accB.x, fmaf(w2, accB.y, w3 * accB.z)));
                float o1 = fmaf(u0, accB.y, fmaf(u1, accB.z, fmaf(u2, accB.w, u3 * rB)));
                reinterpret_cast<float2*>(ob + (2 * p + 1) * OW)[lane] = make_float2(o0, o1);
            }
        }
        return;
    }

    // ===== Generic path (any bbox): weights + striped resize (R7 code) =====
    if (tid < OH + OW) {
        const bool isRow = tid < OH;
        const int  o  = isRow ? tid : tid - OH;
        const float lo = isRow ? s.lo_r : s.lo_c;
        const float hi = isRow ? s.hi_r : s.hi_c;
        const float L       = hi - lo + 1.0f;
        const float scale   = L / 64.0f;
        const float support = fmaxf(scale, 1.0f);
        const float center  = scale * ((float)o + 0.5f);
        const float base    = (lo - 0.5f) + center;
        float a0 = fminf(fmaxf(base - support, -8.0f), 160.0f);
        int j0 = (int)ceilf(a0);
        float wv[TAPS];
        float ssum = 0.0f;
        #pragma unroll
        for (int a = 0; a < TAPS; a++) {
            float jf  = (float)(j0 + a);
            float pos = (jf - lo) + 0.5f;
            float t   = (pos - center) / support;
            float wt  = fmaxf(0.0f, 1.0f - fabsf(t));
            if (!(jf >= lo && jf <= hi)) wt = 0.0f;
            wv[a] = wt;
            ssum += wt;
        }
        float denom = fmaxf(ssum, 1e-12f);
        if (isRow) {
            s.jr[o] = j0;
            #pragma unroll
            for (int a = 0; a < TAPS; a++) s.wh[o][a] = wv[a] / denom;
        } else {
            s.jc[o] = j0;
            #pragma unroll
            for (int a = 0; a < TAPS; a++) s.ww[o][a] = wv[a] / denom;
        }
    }
    __syncthreads();

    float4* tmp4 = reinterpret_cast<float4*>(s.tmp);
    #pragma unroll 1
    for (int st = 0; st < NSTRIPES; st++) {
        {
            int o  = st * STRIPE + wid;
            int wq = lane;
            int j0 = s.jr[o];
            const float* wrow = s.wh[o];
            float4 acc = make_float4(0.f, 0.f, 0.f, 0.f);
            #pragma unroll
            for (int a = 0; a < TAPS; a++) {
                int j = min(max(j0 + a, 0), H - 1);
                float4 v = im4[j * (W / 4) + wq];
                float wt = wrow[a];
                acc.x = fmaf(wt, v.x, acc.x);
                acc.y = fmaf(wt, v.y, acc.y);
                acc.z = fmaf(wt, v.z, acc.z);
                acc.w = fmaf(wt, v.w, acc.w);
            }
            tmp4[wid * (W / 4) + wq] = acc;
        }
        __syncthreads();
        #pragma unroll
        for (int it = 0; it < (STRIPE * OW) / NT; it++) {
            int i = tid + it * NT;
            int ol = i >> 6;
            int p  = i & 63;
            int k0 = s.jc[p];
            const float* wcol = s.ww[p];
            const float* trow = s.tmp + ol * W;
            float acc = 0.0f;
            #pragma unroll
            for (int b = 0; b < TAPS; b++) {
                int kk = min(max(k0 + b, 0), W - 1);
                acc = fmaf(wcol[b], trow[kk], acc);
            }
            ob[(st * STRIPE + ol) * OW + p] = acc;
        }
        __syncthreads();
    }
}

} // anonymous namespace

extern "C" void kernel_launch(void* const* d_in, const int* in_sizes, int n_in,
                              void* d_out, int out_size) {
    const float* x = (const float*)d_in[0];
    float* out = (float*)d_out;
    const int nimg = in_sizes[0] / (H * W);   // N*C = 4096
    cudaFuncSetAttribute(smartpool_kernel,
                         cudaFuncAttributeMaxDynamicSharedMemorySize,
                         (int)sizeof(Smem));
    smartpool_kernel<<<nimg, NT, sizeof(Smem)>>>(x, out);
}

// round 10
// speedup vs baseline: 1.6375x; 1.0134x over previous
#include <cuda_runtime.h>
#include <cstdint>

namespace {

constexpr int H  = 128;
constexpr int W  = 128;
constexpr int OH = 64;
constexpr int OW = 64;
constexpr int NT = 512;          // threads per (persistent) block
constexpr int NW = NT / 32;      // 16 warps
constexpr int IMG4 = H * W / 4;  // 4096 float4 per image
constexpr int K_IT = IMG4 / NT;  // 8 float4 per thread per image
constexpr int TAPS = 4;
constexpr int GRID = 152;        // one persistent CTA per SM (GB300)

// Full-bbox weights (exact): interior [1,3,3,1]/8; edges [3,3,1]/7 pattern.
constexpr float WI0 = 0.125f;
constexpr float WI1 = 0.375f;
constexpr float CE0 = 0.75f / 1.75f;
constexpr float CE1 = 0.25f / 1.75f;

struct Smem {
    float img[2][H * W];        // 128 KB double-buffered image
    float scratch[NW * W];      // 8 KB: colmax partials (stats) / tmp (generic)
    float rowmax[H];
    float wh[OH][TAPS];         // generic-path weights
    float ww[OW][TAPS];
    int   jr[OH], jc[OW];
    float red[3 * NW];
    float thr, lo_r, hi_r, lo_c, hi_c;
};

__device__ __forceinline__ float warpRedMax(float v) {
    #pragma unroll
    for (int s = 16; s > 0; s >>= 1) v = fmaxf(v, __shfl_xor_sync(0xffffffffu, v, s));
    return v;
}
__device__ __forceinline__ float warpRedMin(float v) {
    #pragma unroll
    for (int s = 16; s > 0; s >>= 1) v = fminf(v, __shfl_xor_sync(0xffffffffu, v, s));
    return v;
}

__device__ __forceinline__ void cp16(float4* dst, const float4* src) {
    uint32_t sa = (uint32_t)__cvta_generic_to_shared(dst);
    asm volatile("cp.async.cg.shared.global [%0], [%1], 16;" :: "r"(sa), "l"(src));
}
__device__ __forceinline__ void cp_commit() {
    asm volatile("cp.async.commit_group;");
}
__device__ __forceinline__ void cp_wait0() {
    asm volatile("cp.async.wait_group 0;" ::: "memory");
}

__global__ __launch_bounds__(NT, 1) void smartpool_kernel(const float* __restrict__ x,
                                                          float* __restrict__ out,
                                                          int nimg) {
    extern __shared__ unsigned char raw[];
    Smem& s = *reinterpret_cast<Smem*>(raw);
    const int tid  = threadIdx.x;
    const int wid  = tid >> 5;      // 0..15
    const int lane = tid & 31;

    int img = blockIdx.x;
    if (img >= nimg) return;

    // Prologue: prefetch first image into buffer 0.
    {
        const float4* src = reinterpret_cast<const float4*>(x + (size_t)img * (H * W));
        float4* dst = reinterpret_cast<float4*>(s.img[0]);
        #pragma unroll
        for (int k = 0; k < K_IT; k++) cp16(&dst[tid + k * NT], &src[tid + k * NT]);
        cp_commit();
    }

    int buf = 0;
    for (; img < nimg; img += gridDim.x, buf ^= 1) {
        cp_wait0();
        __syncthreads();   // all threads done with prev iteration; cur buffer visible

        // Prefetch next image into the other buffer (in flight during compute).
        const int nxt = img + gridDim.x;
        if (nxt < nimg) {
            const float4* src = reinterpret_cast<const float4*>(x + (size_t)nxt * (H * W));
            float4* dst = reinterpret_cast<float4*>(s.img[buf ^ 1]);
            #pragma unroll
            for (int k = 0; k < K_IT; k++) cp16(&dst[tid + k * NT], &src[tid + k * NT]);
            cp_commit();
        }

        const float4* im4 = reinterpret_cast<const float4*>(s.img[buf]);

        // ---- Stats: each thread reads only its OWN cp.async'd float4s ----
        // idx = tid + 512k -> row = wid + 16k; lane covers cols [4l, 4l+3].
        // Bbox equivalence (exact): x_min = (min over rows 1..127 >= thr),
        // x_max = max{h>=1: rowmax[h] >= thr} else 0; y_* symmetric on cols.
        float gmax = -3.0e38f, minR = 3.0e38f, minC = 3.0e38f;
        float4 cmax4 = make_float4(-3.0e38f, -3.0e38f, -3.0e38f, -3.0e38f);
        #pragma unroll
        for (int k = 0; k < K_IT; k++) {
            float4 v = im4[tid + k * NT];
            float m4 = fmaxf(fmaxf(v.x, v.y), fmaxf(v.z, v.w));
            float n4 = fminf(fminf(v.x, v.y), fminf(v.z, v.w));
            gmax = fmaxf(gmax, m4);
            cmax4.x = fmaxf(cmax4.x, v.x);
            cmax4.y = fmaxf(cmax4.y, v.y);
            cmax4.z = fmaxf(cmax4.z, v.z);
            cmax4.w = fmaxf(cmax4.w, v.w);
            if (k > 0 || wid != 0) minR = fminf(minR, n4);               // skip row 0
            float nc = (lane == 0) ? fminf(fminf(v.y, v.z), v.w) : n4;   // skip col 0
            minC = fminf(minC, nc);
            float rm = warpRedMax(m4);
            if (lane == 0) s.rowmax[wid + NW * k] = rm;
        }
        reinterpret_cast<float4*>(s.scratch + wid * W)[lane] = cmax4;

        gmax = warpRedMax(gmax);
        minR = warpRedMin(minR);
        minC = warpRedMin(minC);
        if (lane == 0) {
            s.red[wid] = gmax; s.red[NW + wid] = minR; s.red[2 * NW + wid] = minC;
        }
        __syncthreads();
        if (tid == 0) {
            float g = s.red[0], mr = s.red[NW], mc = s.red[2 * NW];
            #pragma unroll
            for (int i = 1; i < NW; i++) {
                g  = fmaxf(g,  s.red[i]);
                mr = fminf(mr, s.red[NW + i]);
                mc = fminf(mc, s.red[2 * NW + i]);
            }
            float thr = 0.1f * g;
            s.thr  = thr;
            s.lo_r = (mr >= thr) ? 1.0f : 0.0f;
            s.lo_c = (mc >= thr) ? 1.0f : 0.0f;
        }
        __syncthreads();
        const float thr = s.thr;

        if (tid < 128) {
            float rm = s.rowmax[tid];
            float cm = s.scratch[tid];
            #pragma unroll
            for (int w = 1; w < NW; w++) cm = fmaxf(cm, s.scratch[w * W + tid]);
            float candR = (tid >= 1 && rm >= thr) ? (float)tid : 0.0f;
            float candC = (tid >= 1 && cm >= thr) ? (float)tid : 0.0f;
            candR = warpRedMax(candR);
            candC = warpRedMax(candC);
            if (lane == 0) { s.red[wid] = candR; s.red[NW + wid] = candC; }
        }
        __syncthreads();
        if (tid == 0) {
            float hr = s.red[0], hc = s.red[NW];
            #pragma unroll
            for (int i = 1; i < 4; i++) {
                hr = fmaxf(hr, s.red[i]); hc = fmaxf(hc, s.red[NW + i]);
            }
            s.hi_r = hr; s.hi_c = hc;
        }
        __syncthreads();

        const bool fastpath = (s.lo_r == 0.0f) && (s.hi_r == 127.0f) &&
                              (s.lo_c == 0.0f) && (s.hi_c == 127.0f);
        float* ob = out + (size_t)img * (OH * OW);

        if (fastpath) {
            // ==== Fast path: fixed [1,3,3,1]/8 stencil (edges [3,3,1]/7). ====
            // Warp computes output-row pair; column resize in registers via
            // shuffles; direct coalesced gmem stores; no barriers.
            const float w0 = (lane == 0)  ? 0.0f : WI0;
            const float w1 = (lane == 0)  ? CE0  : WI1;
            const float w2 = (lane == 0)  ? CE0  : WI1;
            const float w3 = (lane == 0)  ? CE1  : WI0;
            const float u0 = (lane == 31) ? CE1  : WI0;
            const float u1 = (lane == 31) ? CE0  : WI1;
            const float u2 = (lane == 31) ? CE0  : WI1;
            const float u3 = (lane == 31) ? 0.0f : WI0;

            #pragma unroll
            for (int t = 0; t < 2; t++) {
                const int p  = wid + NW * t;      // pair index 0..31
                const int r0 = 4 * p - 1;
                const float a0 = (p == 0)  ? 0.0f : WI0;
                const float a1 = (p == 0)  ? CE0  : WI1;
                const float a2 = (p == 0)  ? CE0  : WI1;
                const float a3 = (p == 0)  ? CE1  : WI0;
                const float b0 = (p == 31) ? CE1  : WI0;
                const float b1 = (p == 31) ? CE0  : WI1;
                const float b2 = (p == 31) ? CE0  : WI1;
                const float b3 = (p == 31) ? 0.0f : WI0;

                float4 accA = make_float4(0.f, 0.f, 0.f, 0.f);
                float4 accB = make_float4(0.f, 0.f, 0.f, 0.f);
                #pragma unroll
                for (int sl = 0; sl < 6; sl++) {
                    int rr = min(max(r0 + sl, 0), H - 1);   // clamped rows: w=0
                    float4 v = im4[rr * (W / 4) + lane];
                    float wa = (sl == 0) ? a0 : (sl == 1) ? a1 : (sl == 2) ? a2
                             : (sl == 3) ? a3 : 0.0f;
                    float wb = (sl == 2) ? b0 : (sl == 3) ? b1 : (sl == 4) ? b2
                             : (sl == 5) ? b3 : 0.0f;
                    if (sl < 4) {
                        accA.x = fmaf(wa, v.x, accA.x);
                        accA.y = fmaf(wa, v.y, accA.y);
                        accA.z = fmaf(wa, v.z, accA.z);
                        accA.w = fmaf(wa, v.w, accA.w);
                    }
                    if (sl >= 2) {
                        accB.x = fmaf(wb, v.x, accB.x);
                        accB.y = fmaf(wb, v.y, accB.y);
                        accB.z = fmaf(wb, v.z, accB.z);
                        accB.w = fmaf(wb, v.w, accB.w);
                    }
                }
                {
                    float lA = __shfl_up_sync(0xffffffffu, accA.w, 1);
                    float rA = __shfl_down_sync(0xffffffffu, accA.x, 1);
                    float o0 = fmaf(w0, lA, fmaf(w1, accA.x, fmaf(w2, accA.y, w3 * accA.z)));
                    float o1 = fmaf(u0, accA.y, fmaf(u1, accA.z, fmaf(u2, accA.w, u3 * rA)));
                    reinterpret_cast<float2*>(ob + (2 * p) * OW)[lane] = make_float2(o0, o1);
                }
                {
                    float lB = __shfl_up_sync(0xffffffffu, accB.w, 1);
                    float rB = __shfl_down_sync(0xffffffffu, accB.x, 1);
                    float o0 = fmaf(w0, lB, fmaf(w1, accB.x, fmaf(w2, accB.y, w3 * accB.z)));
                    float o1 = fmaf(u0, accB.y, fmaf(u1, accB.z, fmaf(u2, accB.w, u3 * rB)));
                    reinterpret_cast<float2*>(ob + (2 * p + 1) * OW)[lane] = make_float2(o0, o1);
                }
            }
        } else {
            // ==== Generic path (any bbox): 4-tap weights + striped resize ====
            if (tid < OH + OW) {
                const bool isRow = tid < OH;
                const int  o  = isRow ? tid : tid - OH;
                const float lo = isRow ? s.lo_r : s.lo_c;
                const float hi = isRow ? s.hi_r : s.hi_c;
                const float L       = hi - lo + 1.0f;
                const float scale   = L / 64.0f;
                const float support = fmaxf(scale, 1.0f);
                const float center  = scale * ((float)o + 0.5f);
                const float base    = (lo - 0.5f) + center;
                float a0 = fminf(fmaxf(base - support, -8.0f), 160.0f);
                int j0 = (int)ceilf(a0);
                float wv[TAPS];
                float ssum = 0.0f;
                #pragma unroll
                for (int a = 0; a < TAPS; a++) {
                    float jf  = (float)(j0 + a);
                    float pos = (jf - lo) + 0.5f;
                    float tt  = (pos - center) / support;
                    float wt  = fmaxf(0.0f, 1.0f - fabsf(tt));
                    if (!(jf >= lo && jf <= hi)) wt = 0.0f;
                    wv[a] = wt;
                    ssum += wt;
                }
                float denom = fmaxf(ssum, 1e-12f);
                if (isRow) {
                    s.jr[o] = j0;
                    #pragma unroll
                    for (int a = 0; a < TAPS; a++) s.wh[o][a] = wv[a] / denom;
                } else {
                    s.jc[o] = j0;
                    #pragma unroll
                    for (int a = 0; a < TAPS; a++) s.ww[o][a] = wv[a] / denom;
                }
            }
            __syncthreads();

            float4* tmp4 = reinterpret_cast<float4*>(s.scratch);
            #pragma unroll 1
            for (int st = 0; st < 4; st++) {          // 4 stripes of 16 rows
                {
                    int o  = st * NW + wid;
                    int j0 = s.jr[o];
                    const float* wrow = s.wh[o];
                    float4 acc = make_float4(0.f, 0.f, 0.f, 0.f);
                    #pragma unroll
                    for (int a = 0; a < TAPS; a++) {
                        int j = min(max(j0 + a, 0), H - 1);
                        float4 v = im4[j * (W / 4) + lane];
                        float wt = wrow[a];
                        acc.x = fmaf(wt, v.x, acc.x);
                        acc.y = fmaf(wt, v.y, acc.y);
                        acc.z = fmaf(wt, v.z, acc.z);
                        acc.w = fmaf(wt, v.w, acc.w);
                    }
                    tmp4[wid * (W / 4) + lane] = acc;
                }
                __syncthreads();
                #pragma unroll
                for (int it = 0; it < (NW * OW) / NT; it++) {
                    int i = tid + it * NT;
                    int ol = i >> 6;
                    int p  = i & 63;
                    int k0 = s.jc[p];
                    const float* wcol = s.ww[p];
                    const float* trow = s.scratch + ol * W;
                    float acc = 0.0f;
                    #pragma unroll
                    for (int b = 0; b < TAPS; b++) {
                        int kk = min(max(k0 + b, 0), W - 1);
                        acc = fmaf(wcol[b], trow[kk], acc);
                    }
                    ob[(st * NW + ol) * OW + p] = acc;
                }
                __syncthreads();
            }
        }
    }
}

} // anonymous namespace

extern "C" void kernel_launch(void* const* d_in, const int* in_sizes, int n_in,
                              void* d_out, int out_size) {
    const float* x = (const float*)d_in[0];
    float* out = (float*)d_out;
    const int nimg = in_sizes[0] / (H * W);   // N*C = 4096
    cudaFuncSetAttribute(smartpool_kernel,
                         cudaFuncAttributeMaxDynamicSharedMemorySize,
                         (int)sizeof(Smem));
    int grid = nimg < GRID ? nimg : GRID;
    smartpool_kernel<<<grid, NT, sizeof(Smem)>>>(x, out, nimg);
}

// round 12
// speedup vs baseline: 1.9552x; 1.1940x over previous
#include <cuda_runtime.h>
#include <cstdint>

namespace {

constexpr int H  = 128;
constexpr int W  = 128;
constexpr int OH = 64;
constexpr int OW = 64;
constexpr int NT = 512;          // threads per persistent block
constexpr int NW = NT / 32;      // 16 warps
constexpr int IMG4 = H * W / 4;  // 4096 float4 per image
constexpr int K_IT = IMG4 / NT;  // 8 float4 per thread per image
constexpr int TAPS = 4;
constexpr int GRID = 152;        // one persistent CTA per SM

// Full-bbox weights (exact): interior [1,3,3,1]/8; edges [3,3,1]/7 pattern.
constexpr float WI0 = 0.125f;
constexpr float WI1 = 0.375f;
constexpr float CE0 = 0.75f / 1.75f;
constexpr float CE1 = 0.25f / 1.75f;

struct Smem {
    float img[2][H * W];        // 128 KB double-buffered image
    float scratch[NW * W];      // 8 KB generic-path tmp
    float wh[OH][TAPS];         // generic-path weights
    float ww[OW][TAPS];
    int   jr[OH], jc[OW];
    float red[3 * NW];
    float thr, lo_r, hi_r, lo_c, hi_c;
};

__device__ __forceinline__ float warpRedMax(float v) {
    #pragma unroll
    for (int s = 16; s > 0; s >>= 1) v = fmaxf(v, __shfl_xor_sync(0xffffffffu, v, s));
    return v;
}
__device__ __forceinline__ float warpRedMin(float v) {
    #pragma unroll
    for (int s = 16; s > 0; s >>= 1) v = fminf(v, __shfl_xor_sync(0xffffffffu, v, s));
    return v;
}

__device__ __forceinline__ void cp16(float4* dst, const float4* src) {
    uint32_t sa = (uint32_t)__cvta_generic_to_shared(dst);
    asm volatile("cp.async.cg.shared.global [%0], [%1], 16;" :: "r"(sa), "l"(src));
}
__device__ __forceinline__ void cp_commit() {
    asm volatile("cp.async.commit_group;");
}
__device__ __forceinline__ void cp_wait0() {
    asm volatile("cp.async.wait_group 0;" ::: "memory");
}

__global__ __launch_bounds__(NT, 1) void smartpool_kernel(const float* __restrict__ x,
                                                          float* __restrict__ out,
                                                          int nimg) {
    extern __shared__ unsigned char raw[];
    Smem& s = *reinterpret_cast<Smem*>(raw);
    const int tid  = threadIdx.x;
    const int wid  = tid >> 5;      // 0..15
    const int lane = tid & 31;

    int img = blockIdx.x;
    if (img >= nimg) return;

    // Prologue: prefetch first image into buffer 0.
    {
        const float4* src = reinterpret_cast<const float4*>(x + (size_t)img * (H * W));
        float4* dst = reinterpret_cast<float4*>(s.img[0]);
        #pragma unroll
        for (int k = 0; k < K_IT; k++) cp16(&dst[tid + k * NT], &src[tid + k * NT]);
        cp_commit();
    }

    int buf = 0;
    for (; img < nimg; img += gridDim.x, buf ^= 1) {
        cp_wait0();
        __syncthreads();   // current buffer visible to all; prev outputs done

        // Prefetch next image (in flight during this image's compute).
        const int nxt = img + gridDim.x;
        if (nxt < nimg) {
            const float4* src = reinterpret_cast<const float4*>(x + (size_t)nxt * (H * W));
            float4* dst = reinterpret_cast<float4*>(s.img[buf ^ 1]);
            #pragma unroll
            for (int k = 0; k < K_IT; k++) cp16(&dst[tid + k * NT], &src[tid + k * NT]);
            cp_commit();
        }

        const float4* im4 = reinterpret_cast<const float4*>(s.img[buf]);

        // ==== Fused pass: speculative fast-path row resize + all statistics ====
        // Warp handles output pairs p = wid and wid+16; tap rows 4p-1..4p+4
        // cover every input row across the block (overlaps are idempotent for
        // max/min stats). Each float4 is read ONCE and feeds both the stencil
        // accumulators and the bbox statistics.
        float gmax = -3.0e38f, minR = 3.0e38f, minC = 3.0e38f;
        float4 cmax = make_float4(-3.0e38f, -3.0e38f, -3.0e38f, -3.0e38f);
        float m4v[2][6];                 // per-read row-segment max (for candR)
        float4 accA[2], accB[2];

        #pragma unroll
        for (int t = 0; t < 2; t++) {
            const int p  = wid + NW * t;       // pair index 0..31
            const int r0 = 4 * p - 1;
            const float a0 = (p == 0)  ? 0.0f : WI0;
            const float a1 = (p == 0)  ? CE0  : WI1;
            const float a2 = (p == 0)  ? CE0  : WI1;
            const float a3 = (p == 0)  ? CE1  : WI0;
            const float b0 = (p == 31) ? CE1  : WI0;
            const float b1 = (p == 31) ? CE0  : WI1;
            const float b2 = (p == 31) ? CE0  : WI1;
            const float b3 = (p == 31) ? 0.0f : WI0;

            accA[t] = make_float4(0.f, 0.f, 0.f, 0.f);
            accB[t] = make_float4(0.f, 0.f, 0.f, 0.f);
            #pragma unroll
            for (int sl = 0; sl < 6; sl++) {
                int rr = min(max(r0 + sl, 0), H - 1);   // clamped rows: weight 0
                float4 v = im4[rr * (W / 4) + lane];
                // --- stats ---
                float mx = fmaxf(fmaxf(v.x, v.y), fmaxf(v.z, v.w));
                float mn = fminf(fminf(v.x, v.y), fminf(v.z, v.w));
                m4v[t][sl] = mx;
                gmax = fmaxf(gmax, mx);
                if (rr != 0) minR = fminf(minR, mn);                        // rows 1..127
                float nc = (lane == 0) ? fminf(fminf(v.y, v.z), v.w) : mn;  // cols 1..127
                minC = fminf(minC, nc);
                cmax.x = fmaxf(cmax.x, v.x);
                cmax.y = fmaxf(cmax.y, v.y);
                cmax.z = fmaxf(cmax.z, v.z);
                cmax.w = fmaxf(cmax.w, v.w);
                // --- speculative fast-path stencil ---
                float wa = (sl == 0) ? a0 : (sl == 1) ? a1 : (sl == 2) ? a2
                         : (sl == 3) ? a3 : 0.0f;
                float wb = (sl == 2) ? b0 : (sl == 3) ? b1 : (sl == 4) ? b2
                         : (sl == 5) ? b3 : 0.0f;
                if (sl < 4) {
                    accA[t].x = fmaf(wa, v.x, accA[t].x);
                    accA[t].y = fmaf(wa, v.y, accA[t].y);
                    accA[t].z = fmaf(wa, v.z, accA[t].z);
                    accA[t].w = fmaf(wa, v.w, accA[t].w);
                }
                if (sl >= 2) {
                    accB[t].x = fmaf(wb, v.x, accB[t].x);
                    accB[t].y = fmaf(wb, v.y, accB[t].y);
                    accB[t].z = fmaf(wb, v.z, accB[t].z);
                    accB[t].w = fmaf(wb, v.w, accB[t].w);
                }
            }
        }

        // ---- Reduction round 1: gmax / minR / minC -> thr, lo_r, lo_c ----
        {
            float g = warpRedMax(gmax);
            float r = warpRedMin(minR);
            float c = warpRedMin(minC);
            if (lane == 0) {
                s.red[wid] = g; s.red[NW + wid] = r; s.red[2 * NW + wid] = c;
            }
        }
        __syncthreads();
        if (wid == 0) {
            float g = (lane < NW) ? s.red[lane]          : -3.0e38f;
            float r = (lane < NW) ? s.red[NW + lane]     :  3.0e38f;
            float c = (lane < NW) ? s.red[2 * NW + lane] :  3.0e38f;
            g = warpRedMax(g); r = warpRedMin(r); c = warpRedMin(c);
            if (lane == 0) {
                float thr = 0.1f * g;
                s.thr  = thr;
                s.lo_r = (r >= thr) ? 1.0f : 0.0f;
                s.lo_c = (c >= thr) ? 1.0f : 0.0f;
            }
        }
        __syncthreads();
        const float thr = s.thr;

        // ---- Reduction round 2: hi_r / hi_c from register stats ----
        {
            float candR = 0.0f, candC = 0.0f;
            #pragma unroll
            for (int t = 0; t < 2; t++) {
                const int r0 = 4 * (wid + NW * t) - 1;
                #pragma unroll
                for (int sl = 0; sl < 6; sl++) {
                    int rr = min(max(r0 + sl, 0), H - 1);
                    if (rr >= 1 && m4v[t][sl] >= thr) candR = fmaxf(candR, (float)rr);
                }
            }
            const float base = (float)(4 * lane);
            if (lane > 0 && cmax.x >= thr) candC = fmaxf(candC, base);
            if (cmax.y >= thr) candC = fmaxf(candC, base + 1.0f);
            if (cmax.z >= thr) candC = fmaxf(candC, base + 2.0f);
            if (cmax.w >= thr) candC = fmaxf(candC, base + 3.0f);
            candR = warpRedMax(candR);
            candC = warpRedMax(candC);
            if (lane == 0) { s.red[wid] = candR; s.red[NW + wid] = candC; }
        }
        __syncthreads();
        if (wid == 0) {
            float hr = (lane < NW) ? s.red[lane]      : 0.0f;
            float hc = (lane < NW) ? s.red[NW + lane] : 0.0f;
            hr = warpRedMax(hr); hc = warpRedMax(hc);
            if (lane == 0) { s.hi_r = hr; s.hi_c = hc; }
        }
        __syncthreads();

        const bool fastpath = (s.lo_r == 0.0f) && (s.hi_r == 127.0f) &&
                              (s.lo_c == 0.0f) && (s.hi_c == 127.0f);
        float* ob = out + (size_t)img * (OH * OW);

        if (fastpath) {
            // Column resize in registers from the speculative accumulators.
            const float w0 = (lane == 0)  ? 0.0f : WI0;
            const float w1 = (lane == 0)  ? CE0  : WI1;
            const float w2 = (lane == 0)  ? CE0  : WI1;
            const float w3 = (lane == 0)  ? CE1  : WI0;
            const float u0 = (lane == 31) ? CE1  : WI0;
            const float u1 = (lane == 31) ? CE0  : WI1;
            const float u2 = (lane == 31) ? CE0  : WI1;
            const float u3 = (lane == 31) ? 0.0f : WI0;
            #pragma unroll
            for (int t = 0; t < 2; t++) {
                const int p = wid + NW * t;
                {
                    float lA = __shfl_up_sync(0xffffffffu, accA[t].w, 1);
                    float rA = __shfl_down_sync(0xffffffffu, accA[t].x, 1);
                    float o0 = fmaf(w0, lA, fmaf(w1, accA[t].x, fmaf(w2, accA[t].y, w3 * accA[t].z)));
                    float o1 = fmaf(u0, accA[t].y, fmaf(u1, accA[t].z, fmaf(u2, accA[t].w, u3 * rA)));
                    reinterpret_cast<float2*>(ob + (2 * p) * OW)[lane] = make_float2(o0, o1);
                }
                {
                    float lB = __shfl_up_sync(0xffffffffu, accB[t].w, 1);
                    float rB = __shfl_down_sync(0xffffffffu, accB[t].x, 1);
                    float o0 = fmaf(w0, lB, fmaf(w1, accB[t].x, fmaf(w2, accB[t].y, w3 * accB[t].z)));
                    float o1 = fmaf(u0, accB[t].y, fmaf(u1, accB[t].z, fmaf(u2, accB[t].w, u3 * rB)));
                    reinterpret_cast<float2*>(ob + (2 * p + 1) * OW)[lane] = make_float2(o0, o1);
                }
            }
        } else {
            // ==== Generic path (any bbox): exact 4-tap weights + striped resize ====
            if (tid < OH + OW) {
                const bool isRow = tid < OH;
                const int  o  = isRow ? tid : tid - OH;
                const float lo = isRow ? s.lo_r : s.lo_c;
                const float hi = isRow ? s.hi_r : s.hi_c;
                const float L       = hi - lo + 1.0f;
                const float scale   = L / 64.0f;
                const float support = fmaxf(scale, 1.0f);
                const float center  = scale * ((float)o + 0.5f);
                const float base    = (lo - 0.5f) + center;
                float a0f = fminf(fmaxf(base - support, -8.0f), 160.0f);
                int j0 = (int)ceilf(a0f);
                float wv[TAPS];
                float ssum = 0.0f;
                #pragma unroll
                for (int a = 0; a < TAPS; a++) {
                    float jf  = (float)(j0 + a);
                    float pos = (jf - lo) + 0.5f;
                    float tt  = (pos - center) / support;
                    float wt  = fmaxf(0.0f, 1.0f - fabsf(tt));
                    if (!(jf >= lo && jf <= hi)) wt = 0.0f;
                    wv[a] = wt;
                    ssum += wt;
                }
                float denom = fmaxf(ssum, 1e-12f);
                if (isRow) {
                    s.jr[o] = j0;
                    #pragma unroll
                    for (int a = 0; a < TAPS; a++) s.wh[o][a] = wv[a] / denom;
                } else {
                    s.jc[o] = j0;
                    #pragma unroll
                    for (int a = 0; a < TAPS; a++) s.ww[o][a] = wv[a] / denom;
                }
            }
            __syncthreads();

            float4* tmp4 = reinterpret_cast<float4*>(s.scratch);
            #pragma unroll 1
            for (int st = 0; st < 4; st++) {          // 4 stripes of 16 rows
                {
                    int o  = st * NW + wid;
                    int j0 = s.jr[o];
                    const float* wrow = s.wh[o];
                    float4 acc = make_float4(0.f, 0.f, 0.f, 0.f);
                    #pragma unroll
                    for (int a = 0; a < TAPS; a++) {
                        int j = min(max(j0 + a, 0), H - 1);
                        float4 v = im4[j * (W / 4) + lane];
                        float wt = wrow[a];
                        acc.x = fmaf(wt, v.x, acc.x);
                        acc.y = fmaf(wt, v.y, acc.y);
                        acc.z = fmaf(wt, v.z, acc.z);
                        acc.w = fmaf(wt, v.w, acc.w);
                    }
                    tmp4[wid * (W / 4) + lane] = acc;
                }
                __syncthreads();
                #pragma unroll
                for (int it = 0; it < (NW * OW) / NT; it++) {
                    int i = tid + it * NT;
                    int ol = i >> 6;
                    int p  = i & 63;
                    int k0 = s.jc[p];
                    const float* wcol = s.ww[p];
                    const float* trow = s.scratch + ol * W;
                    float acc = 0.0f;
                    #pragma unroll
                    for (int b = 0; b < TAPS; b++) {
                        int kk = min(max(k0 + b, 0), W - 1);
                        acc = fmaf(wcol[b], trow[kk], acc);
                    }
                    ob[(st * NW + ol) * OW + p] = acc;
                }
                __syncthreads();
            }
        }
    }
}

} // anonymous namespace

extern "C" void kernel_launch(void* const* d_in, const int* in_sizes, int n_in,
                              void* d_out, int out_size) {
    const float* x = (const float*)d_in[0];
    float* out = (float*)d_out;
    const int nimg = in_sizes[0] / (H * W);   // N*C = 4096
    cudaFuncSetAttribute(smartpool_kernel,
                         cudaFuncAttributeMaxDynamicSharedMemorySize,
                         (int)sizeof(Smem));
    int grid = nimg < GRID ? nimg : GRID;
    smartpool_kernel<<<grid, NT, sizeof(Smem)>>>(x, out, nimg);
}

// round 14
// speedup vs baseline: 2.0680x; 1.0577x over previous
#include <cuda_runtime.h>
#include <cstdint>

namespace {

constexpr int H  = 128;
constexpr int W  = 128;
constexpr int OH = 64;
constexpr int OW = 64;
constexpr int NT = 512;          // threads per persistent block
constexpr int NW = NT / 32;      // 16 warps
constexpr int IMG4 = H * W / 4;  // 4096 float4 per image
constexpr int K_IT = IMG4 / NT;  // 8 float4 per thread per image
constexpr int TAPS = 4;
constexpr int GRID = 152;        // one persistent CTA per SM

// Full-bbox weights (exact): interior [1,3,3,1]/8; edges [3,3,1]/7 pattern.
constexpr float WI0 = 0.125f;
constexpr float WI1 = 0.375f;
constexpr float CE0 = 0.75f / 1.75f;
constexpr float CE1 = 0.25f / 1.75f;

struct Smem {
    float img[2][H * W];        // 128 KB double-buffered image
    float scratch[NW * W];      // 8 KB generic-path tmp
    float wh[OH][TAPS];         // generic-path weights
    float ww[OW][TAPS];
    int   jr[OH], jc[OW];
    float red[3 * NW];
    float thr, lo_r, hi_r, lo_c, hi_c;
};

__device__ __forceinline__ float warpRedMax(float v) {
    #pragma unroll
    for (int s = 16; s > 0; s >>= 1) v = fmaxf(v, __shfl_xor_sync(0xffffffffu, v, s));
    return v;
}
__device__ __forceinline__ float warpRedMin(float v) {
    #pragma unroll
    for (int s = 16; s > 0; s >>= 1) v = fminf(v, __shfl_xor_sync(0xffffffffu, v, s));
    return v;
}

__device__ __forceinline__ void cp16(float4* dst, const float4* src) {
    uint32_t sa = (uint32_t)__cvta_generic_to_shared(dst);
    asm volatile("cp.async.cg.shared.global [%0], [%1], 16;" :: "r"(sa), "l"(src));
}
__device__ __forceinline__ void cp_commit() {
    asm volatile("cp.async.commit_group;");
}
__device__ __forceinline__ void cp_wait0() {
    asm volatile("cp.async.wait_group 0;" ::: "memory");
}

__global__ __launch_bounds__(NT, 1) void smartpool_kernel(const float* __restrict__ x,
                                                          float* __restrict__ out,
                                                          int nimg) {
    extern __shared__ unsigned char raw[];
    Smem& s = *reinterpret_cast<Smem*>(raw);
    const int tid  = threadIdx.x;
    const int wid  = tid >> 5;      // 0..15
    const int lane = tid & 31;

    int img = blockIdx.x;
    if (img >= nimg) return;

    // Prologue: prefetch first image into buffer 0.
    {
        const float4* src = reinterpret_cast<const float4*>(x + (size_t)img * (H * W));
        float4* dst = reinterpret_cast<float4*>(s.img[0]);
        #pragma unroll
        for (int k = 0; k < K_IT; k++) cp16(&dst[tid + k * NT], &src[tid + k * NT]);
        cp_commit();
    }

    int buf = 0;
    for (; img < nimg; img += gridDim.x, buf ^= 1) {
        cp_wait0();
        __syncthreads();   // current buffer visible; prev outputs done

        // Prefetch next image (in flight during this image's compute).
        const int nxt = img + gridDim.x;
        if (nxt < nimg) {
            const float4* src = reinterpret_cast<const float4*>(x + (size_t)nxt * (H * W));
            float4* dst = reinterpret_cast<float4*>(s.img[buf ^ 1]);
            #pragma unroll
            for (int k = 0; k < K_IT; k++) cp16(&dst[tid + k * NT], &src[tid + k * NT]);
            cp_commit();
        }

        const float4* im4 = reinterpret_cast<const float4*>(s.img[buf]);

        // ==== Fused pass: speculative row stencil + owned-slot statistics ====
        // Warp handles output pairs p = wid, wid+16; taps span rows 4p-1..4p+4.
        // Slots sl=1..4 "own" rows 4p..4p+3: a perfect partition of all 128
        // rows across the block, so stats on owned slots only cover every
        // element exactly once. Slots 0 and 5 are stencil-only.
        float4 cmax = make_float4(-3.0e38f, -3.0e38f, -3.0e38f, -3.0e38f);
        float4 cmin = make_float4( 3.0e38f,  3.0e38f,  3.0e38f,  3.0e38f);  // rows 1..127
        float4 r0v  = make_float4( 3.0e38f,  3.0e38f,  3.0e38f,  3.0e38f);  // row 0 (warp 0)
        float  m4v[2][4];                 // owned-row segment max
        float4 accA[2], accB[2];

        #pragma unroll
        for (int t = 0; t < 2; t++) {
            const int p  = wid + NW * t;       // pair index 0..31
            const int r0 = 4 * p - 1;
            const float a0 = (p == 0)  ? 0.0f : WI0;
            const float a1 = (p == 0)  ? CE0  : WI1;
            const float a2 = (p == 0)  ? CE0  : WI1;
            const float a3 = (p == 0)  ? CE1  : WI0;
            const float b0 = (p == 31) ? CE1  : WI0;
            const float b1 = (p == 31) ? CE0  : WI1;
            const float b2 = (p == 31) ? CE0  : WI1;
            const float b3 = (p == 31) ? 0.0f : WI0;

            accA[t] = make_float4(0.f, 0.f, 0.f, 0.f);
            accB[t] = make_float4(0.f, 0.f, 0.f, 0.f);
            #pragma unroll
            for (int sl = 0; sl < 6; sl++) {
                int rr = min(max(r0 + sl, 0), H - 1);   // clamped rows: weight 0
                float4 v = im4[rr * (W / 4) + lane];
                // --- stats on owned slots only (rows 4p .. 4p+3) ---
                if (sl >= 1 && sl <= 4) {
                    cmax.x = fmaxf(cmax.x, v.x);
                    cmax.y = fmaxf(cmax.y, v.y);
                    cmax.z = fmaxf(cmax.z, v.z);
                    cmax.w = fmaxf(cmax.w, v.w);
                    const bool isRow0 = (t == 0) && (sl == 1) && (wid == 0);
                    if (!isRow0) {
                        cmin.x = fminf(cmin.x, v.x);
                        cmin.y = fminf(cmin.y, v.y);
                        cmin.z = fminf(cmin.z, v.z);
                        cmin.w = fminf(cmin.w, v.w);
                    } else {
                        r0v = v;
                    }
                    m4v[t][sl - 1] = fmaxf(fmaxf(v.x, v.y), fmaxf(v.z, v.w));
                }
                // --- speculative fast-path stencil ---
                float wa = (sl == 0) ? a0 : (sl == 1) ? a1 : (sl == 2) ? a2
                         : (sl == 3) ? a3 : 0.0f;
                float wb = (sl == 2) ? b0 : (sl == 3) ? b1 : (sl == 4) ? b2
                         : (sl == 5) ? b3 : 0.0f;
                if (sl < 4) {
                    accA[t].x = fmaf(wa, v.x, accA[t].x);
                    accA[t].y = fmaf(wa, v.y, accA[t].y);
                    accA[t].z = fmaf(wa, v.z, accA[t].z);
                    accA[t].w = fmaf(wa, v.w, accA[t].w);
                }
                if (sl >= 2) {
                    accB[t].x = fmaf(wb, v.x, accB[t].x);
                    accB[t].y = fmaf(wb, v.y, accB[t].y);
                    accB[t].z = fmaf(wb, v.z, accB[t].z);
                    accB[t].w = fmaf(wb, v.w, accB[t].w);
                }
            }
        }

        // ---- Post-loop per-thread stats ----
        // gmax from owned segment maxima (covers all rows exactly once; row 0's
        // max is inside warp 0's m4v[0][0]).
        float gmax = fmaxf(fmaxf(fmaxf(m4v[0][0], m4v[0][1]), fmaxf(m4v[0][2], m4v[0][3])),
                           fmaxf(fmaxf(m4v[1][0], m4v[1][1]), fmaxf(m4v[1][2], m4v[1][3])));
        // minR: min over rows 1..127 = hmin of cmin (row 0 diverted to r0v).
        float minR = fminf(fminf(cmin.x, cmin.y), fminf(cmin.z, cmin.w));
        // colmin over ALL rows (fold row 0 back in; r0v = +inf except warp 0).
        float4 colmin;
        colmin.x = fminf(cmin.x, r0v.x);
        colmin.y = fminf(cmin.y, r0v.y);
        colmin.z = fminf(cmin.z, r0v.z);
        colmin.w = fminf(cmin.w, r0v.w);
        // minC: min over cols 1..127 (lane 0 excludes its col 0 = colmin.x).
        float minC = (lane == 0)
                   ? fminf(fminf(colmin.y, colmin.z), colmin.w)
                   : fminf(fminf(colmin.x, colmin.y), fminf(colmin.z, colmin.w));

        // ---- Reduction round 1: gmax / minR / minC -> thr, lo_r, lo_c ----
        {
            float g = warpRedMax(gmax);
            float r = warpRedMin(minR);
            float c = warpRedMin(minC);
            if (lane == 0) {
                s.red[wid] = g; s.red[NW + wid] = r; s.red[2 * NW + wid] = c;
            }
        }
        __syncthreads();
        if (wid == 0) {
            float g = (lane < NW) ? s.red[lane]          : -3.0e38f;
            float r = (lane < NW) ? s.red[NW + lane]     :  3.0e38f;
            float c = (lane < NW) ? s.red[2 * NW + lane] :  3.0e38f;
            g = warpRedMax(g); r = warpRedMin(r); c = warpRedMin(c);
            if (lane == 0) {
                float thr = 0.1f * g;
                s.thr  = thr;
                s.lo_r = (r >= thr) ? 1.0f : 0.0f;
                s.lo_c = (c >= thr) ? 1.0f : 0.0f;
            }
        }
        __syncthreads();
        const float thr = s.thr;

        // ---- Reduction round 2: hi_r / hi_c from register stats ----
        {
            float candR = 0.0f, candC = 0.0f;
            #pragma unroll
            for (int t = 0; t < 2; t++) {
                #pragma unroll
                for (int j = 0; j < 4; j++) {
                    int rr = 4 * (wid + NW * t) + j;     // owned row
                    if (rr >= 1 && m4v[t][j] >= thr) candR = fmaxf(candR, (float)rr);
                }
            }
            const float base = (float)(4 * lane);
            if (lane > 0 && cmax.x >= thr) candC = fmaxf(candC, base);
            if (cmax.y >= thr) candC = fmaxf(candC, base + 1.0f);
            if (cmax.z >= thr) candC = fmaxf(candC, base + 2.0f);
            if (cmax.w >= thr) candC = fmaxf(candC, base + 3.0f);
            candR = warpRedMax(candR);
            candC = warpRedMax(candC);
            if (lane == 0) { s.red[wid] = candR; s.red[NW + wid] = candC; }
        }
        __syncthreads();
        if (wid == 0) {
            float hr = (lane < NW) ? s.red[lane]      : 0.0f;
            float hc = (lane < NW) ? s.red[NW + lane] : 0.0f;
            hr = warpRedMax(hr); hc = warpRedMax(hc);
            if (lane == 0) { s.hi_r = hr; s.hi_c = hc; }
        }
        __syncthreads();

        const bool fastpath = (s.lo_r == 0.0f) && (s.hi_r == 127.0f) &&
                              (s.lo_c == 0.0f) && (s.hi_c == 127.0f);
        float* ob = out + (size_t)img * (OH * OW);

        if (fastpath) {
            // Column resize in registers from the speculative accumulators.
            const float w0 = (lane == 0)  ? 0.0f : WI0;
            const float w1 = (lane == 0)  ? CE0  : WI1;
            const float w2 = (lane == 0)  ? CE0  : WI1;
            const float w3 = (lane == 0)  ? CE1  : WI0;
            const float u0 = (lane == 31) ? CE1  : WI0;
            const float u1 = (lane == 31) ? CE0  : WI1;
            const float u2 = (lane == 31) ? CE0  : WI1;
            const float u3 = (lane == 31) ? 0.0f : WI0;
            #pragma unroll
            for (int t = 0; t < 2; t++) {
                const int p = wid + NW * t;
                {
                    float lA = __shfl_up_sync(0xffffffffu, accA[t].w, 1);
                    float rA = __shfl_down_sync(0xffffffffu, accA[t].x, 1);
                    float o0 = fmaf(w0, lA, fmaf(w1, accA[t].x, fmaf(w2, accA[t].y, w3 * accA[t].z)));
                    float o1 = fmaf(u0, accA[t].y, fmaf(u1, accA[t].z, fmaf(u2, accA[t].w, u3 * rA)));
                    reinterpret_cast<float2*>(ob + (2 * p) * OW)[lane] = make_float2(o0, o1);
                }
                {
                    float lB = __shfl_up_sync(0xffffffffu, accB[t].w, 1);
                    float rB = __shfl_down_sync(0xffffffffu, accB[t].x, 1);
                    float o0 = fmaf(w0, lB, fmaf(w1, accB[t].x, fmaf(w2, accB[t].y, w3 * accB[t].z)));
                    float o1 = fmaf(u0, accB[t].y, fmaf(u1, accB[t].z, fmaf(u2, accB[t].w, u3 * rB)));
                    reinterpret_cast<float2*>(ob + (2 * p + 1) * OW)[lane] = make_float2(o0, o1);
                }
            }
        } else {
            // ==== Generic path (any bbox): exact 4-tap weights + striped resize ====
            if (tid < OH + OW) {
                const bool isRow = tid < OH;
                const int  o  = isRow ? tid : tid - OH;
                const float lo = isRow ? s.lo_r : s.lo_c;
                const float hi = isRow ? s.hi_r : s.hi_c;
                const float L       = hi - lo + 1.0f;
                const float scale   = L / 64.0f;
                const float support = fmaxf(scale, 1.0f);
                const float center  = scale * ((float)o + 0.5f);
                const float base    = (lo - 0.5f) + center;
                float a0f = fminf(fmaxf(base - support, -8.0f), 160.0f);
                int j0 = (int)ceilf(a0f);
                float wv[TAPS];
                float ssum = 0.0f;
                #pragma unroll
                for (int a = 0; a < TAPS; a++) {
                    float jf  = (float)(j0 + a);
                    float pos = (jf - lo) + 0.5f;
                    float tt  = (pos - center) / support;
                    float wt  = fmaxf(0.0f, 1.0f - fabsf(tt));
                    if (!(jf >= lo && jf <= hi)) wt = 0.0f;
                    wv[a] = wt;
                    ssum += wt;
                }
                float denom = fmaxf(ssum, 1e-12f);
                if (isRow) {
                    s.jr[o] = j0;
                    #pragma unroll
                    for (int a = 0; a < TAPS; a++) s.wh[o][a] = wv[a] / denom;
                } else {
                    s.jc[o] = j0;
                    #pragma unroll
                    for (int a = 0; a < TAPS; a++) s.ww[o][a] = wv[a] / denom;
                }
            }
            __syncthreads();

            float4* tmp4 = reinterpret_cast<float4*>(s.scratch);
            #pragma unroll 1
            for (int st = 0; st < 4; st++) {          // 4 stripes of 16 rows
                {
                    int o  = st * NW + wid;
                    int j0 = s.jr[o];
                    const float* wrow = s.wh[o];
                    float4 acc = make_float4(0.f, 0.f, 0.f, 0.f);
                    #pragma unroll
                    for (int a = 0; a < TAPS; a++) {
                        int j = min(max(j0 + a, 0), H - 1);
                        float4 v = im4[j * (W / 4) + lane];
                        float wt = wrow[a];
                        acc.x = fmaf(wt, v.x, acc.x);
                        acc.y = fmaf(wt, v.y, acc.y);
                        acc.z = fmaf(wt, v.z, acc.z);
                        acc.w = fmaf(wt, v.w, acc.w);
                    }
                    tmp4[wid * (W / 4) + lane] = acc;
                }
                __syncthreads();
                #pragma unroll
                for (int it = 0; it < (NW * OW) / NT; it++) {
                    int i = tid + it * NT;
                    int ol = i >> 6;
                    int p  = i & 63;
                    int k0 = s.jc[p];
                    const float* wcol = s.ww[p];
                    const float* trow = s.scratch + ol * W;
                    float acc = 0.0f;
                    #pragma unroll
                    for (int b = 0; b < TAPS; b++) {
                        int kk = min(max(k0 + b, 0), W - 1);
                        acc = fmaf(wcol[b], trow[kk], acc);
                    }
                    ob[(st * NW + ol) * OW + p] = acc;
                }
                __syncthreads();
            }
        }
    }
}

} // anonymous namespace

extern "C" void kernel_launch(void* const* d_in, const int* in_sizes, int n_in,
                              void* d_out, int out_size) {
    const float* x = (const float*)d_in[0];
    float* out = (float*)d_out;
    const int nimg = in_sizes[0] / (H * W);   // N*C = 4096
    cudaFuncSetAttribute(smartpool_kernel,
                         cudaFuncAttributeMaxDynamicSharedMemorySize,
                         (int)sizeof(Smem));
    int grid = nimg < GRID ? nimg : GRID;
    smartpool_kernel<<<grid, NT, sizeof(Smem)>>>(x, out, nimg);
}

// round 15
// speedup vs baseline: 2.1012x; 1.0160x over previous
#include <cuda_runtime.h>
#include <cstdint>

namespace {

constexpr int H  = 128;
constexpr int W  = 128;
constexpr int OH = 64;
constexpr int OW = 64;
constexpr int NT = 512;          // threads per persistent block
constexpr int NW = NT / 32;      // 16 warps
constexpr int IMG4 = H * W / 4;  // 4096 float4 per image
constexpr int K_IT = IMG4 / NT;  // 8 float4 per thread per image
constexpr int TAPS = 4;
constexpr int GRID = 152;        // one persistent CTA per SM

// Full-bbox weights (exact): interior [1,3,3,1]/8; edges [3,3,1]/7 pattern.
constexpr float WI0 = 0.125f;
constexpr float WI1 = 0.375f;
constexpr float CE0 = 0.75f / 1.75f;
constexpr float CE1 = 0.25f / 1.75f;

struct Smem {
    float img[2][H * W];        // 128 KB double-buffered image
    float scratch[NW * W];      // 8 KB generic-path tmp
    float wh[OH][TAPS];         // generic-path weights
    float ww[OW][TAPS];
    int   jr[OH], jc[OW];
    float red[5 * NW];
    float thr, lo_r, lo_c, hi_r, hi_c;
    int   fastflag;
};

__device__ __forceinline__ float warpRedMax(float v) {
    #pragma unroll
    for (int s = 16; s > 0; s >>= 1) v = fmaxf(v, __shfl_xor_sync(0xffffffffu, v, s));
    return v;
}
__device__ __forceinline__ float warpRedMin(float v) {
    #pragma unroll
    for (int s = 16; s > 0; s >>= 1) v = fminf(v, __shfl_xor_sync(0xffffffffu, v, s));
    return v;
}

__device__ __forceinline__ void cp16(float4* dst, const float4* src) {
    uint32_t sa = (uint32_t)__cvta_generic_to_shared(dst);
    asm volatile("cp.async.cg.shared.global [%0], [%1], 16;" :: "r"(sa), "l"(src));
}
__device__ __forceinline__ void cp_commit() {
    asm volatile("cp.async.commit_group;");
}
__device__ __forceinline__ void cp_wait0() {
    asm volatile("cp.async.wait_group 0;" ::: "memory");
}

__global__ __launch_bounds__(NT, 1) void smartpool_kernel(const float* __restrict__ x,
                                                          float* __restrict__ out,
                                                          int nimg) {
    extern __shared__ unsigned char raw[];
    Smem& s = *reinterpret_cast<Smem*>(raw);
    const int tid  = threadIdx.x;
    const int wid  = tid >> 5;      // 0..15
    const int lane = tid & 31;

    int img = blockIdx.x;
    if (img >= nimg) return;

    // Prologue: prefetch first image into buffer 0.
    {
        const float4* src = reinterpret_cast<const float4*>(x + (size_t)img * (H * W));
        float4* dst = reinterpret_cast<float4*>(s.img[0]);
        #pragma unroll
        for (int k = 0; k < K_IT; k++) cp16(&dst[tid + k * NT], &src[tid + k * NT]);
        cp_commit();
    }

    int buf = 0;
    for (; img < nimg; img += gridDim.x, buf ^= 1) {
        cp_wait0();
        __syncthreads();   // current buffer visible; prev outputs done

        // Prefetch next image (in flight during this image's compute).
        const int nxt = img + gridDim.x;
        if (nxt < nimg) {
            const float4* src = reinterpret_cast<const float4*>(x + (size_t)nxt * (H * W));
            float4* dst = reinterpret_cast<float4*>(s.img[buf ^ 1]);
            #pragma unroll
            for (int k = 0; k < K_IT; k++) cp16(&dst[tid + k * NT], &src[tid + k * NT]);
            cp_commit();
        }

        const float4* im4 = reinterpret_cast<const float4*>(s.img[buf]);

        // ==== Fused pass: speculative row stencil + owned-slot statistics ====
        // Warp handles output pairs p = wid, wid+16; taps span rows 4p-1..4p+4.
        // Slots sl=1..4 own rows 4p..4p+3: perfect partition of all 128 rows,
        // so owned-slot stats cover every element exactly once. Slots 0 and 5
        // are stencil-only.
        float4 cmax = make_float4(-3.0e38f, -3.0e38f, -3.0e38f, -3.0e38f);
        float4 cmin = make_float4( 3.0e38f,  3.0e38f,  3.0e38f,  3.0e38f);  // rows 1..127
        float4 r0v  = make_float4( 3.0e38f,  3.0e38f,  3.0e38f,  3.0e38f);  // row 0 (warp 0)
        float  m4v[2][4];                 // owned-row segment max
        float4 accA[2], accB[2];

        #pragma unroll
        for (int t = 0; t < 2; t++) {
            const int p  = wid + NW * t;       // pair index 0..31
            const int r0 = 4 * p - 1;
            const float a0 = (p == 0)  ? 0.0f : WI0;
            const float a1 = (p == 0)  ? CE0  : WI1;
            const float a2 = (p == 0)  ? CE0  : WI1;
            const float a3 = (p == 0)  ? CE1  : WI0;
            const float b0 = (p == 31) ? CE1  : WI0;
            const float b1 = (p == 31) ? CE0  : WI1;
            const float b2 = (p == 31) ? CE0  : WI1;
            const float b3 = (p == 31) ? 0.0f : WI0;

            accA[t] = make_float4(0.f, 0.f, 0.f, 0.f);
            accB[t] = make_float4(0.f, 0.f, 0.f, 0.f);
            #pragma unroll
            for (int sl = 0; sl < 6; sl++) {
                int rr = min(max(r0 + sl, 0), H - 1);   // clamped rows: weight 0
                float4 v = im4[rr * (W / 4) + lane];
                // --- stats on owned slots only (rows 4p .. 4p+3) ---
                if (sl >= 1 && sl <= 4) {
                    cmax.x = fmaxf(cmax.x, v.x);
                    cmax.y = fmaxf(cmax.y, v.y);
                    cmax.z = fmaxf(cmax.z, v.z);
                    cmax.w = fmaxf(cmax.w, v.w);
                    const bool isRow0 = (t == 0) && (sl == 1) && (wid == 0);
                    if (!isRow0) {
                        cmin.x = fminf(cmin.x, v.x);
                        cmin.y = fminf(cmin.y, v.y);
                        cmin.z = fminf(cmin.z, v.z);
                        cmin.w = fminf(cmin.w, v.w);
                    } else {
                        r0v = v;
                    }
                    m4v[t][sl - 1] = fmaxf(fmaxf(v.x, v.y), fmaxf(v.z, v.w));
                }
                // --- speculative fast-path stencil ---
                float wa = (sl == 0) ? a0 : (sl == 1) ? a1 : (sl == 2) ? a2
                         : (sl == 3) ? a3 : 0.0f;
                float wb = (sl == 2) ? b0 : (sl == 3) ? b1 : (sl == 4) ? b2
                         : (sl == 5) ? b3 : 0.0f;
                if (sl < 4) {
                    accA[t].x = fmaf(wa, v.x, accA[t].x);
                    accA[t].y = fmaf(wa, v.y, accA[t].y);
                    accA[t].z = fmaf(wa, v.z, accA[t].z);
                    accA[t].w = fmaf(wa, v.w, accA[t].w);
                }
                if (sl >= 2) {
                    accB[t].x = fmaf(wb, v.x, accB[t].x);
                    accB[t].y = fmaf(wb, v.y, accB[t].y);
                    accB[t].z = fmaf(wb, v.z, accB[t].z);
                    accB[t].w = fmaf(wb, v.w, accB[t].w);
                }
            }
        }

        // ---- Post-loop per-thread stats ----
        float gmax = fmaxf(fmaxf(fmaxf(m4v[0][0], m4v[0][1]), fmaxf(m4v[0][2], m4v[0][3])),
                           fmaxf(fmaxf(m4v[1][0], m4v[1][1]), fmaxf(m4v[1][2], m4v[1][3])));
        float minR = fminf(fminf(cmin.x, cmin.y), fminf(cmin.z, cmin.w));
        float4 colmin;   // all rows (fold row 0 back; r0v = +inf except warp 0)
        colmin.x = fminf(cmin.x, r0v.x);
        colmin.y = fminf(cmin.y, r0v.y);
        colmin.z = fminf(cmin.z, r0v.z);
        colmin.w = fminf(cmin.w, r0v.w);
        float minC = (lane == 0)
                   ? fminf(fminf(colmin.y, colmin.z), colmin.w)
                   : fminf(fminf(colmin.x, colmin.y), fminf(colmin.z, colmin.w));
        // Fast-path decision needs only two extra maxima (thr-independent):
        //   hi_r==127 <=> rowmax[127] >= thr ; row 127 = warp15, m4v[1][3]
        //   hi_c==127 <=> colmax[127] >= thr ; col 127 = lane31's cmax.w
        float r127 = (wid == 15) ? m4v[1][3] : -3.0e38f;
        float c127 = (lane == 31) ? cmax.w   : -3.0e38f;

        // ---- Single reduction round: 5 quantities ----
        {
            float g  = warpRedMax(gmax);
            float r  = warpRedMin(minR);
            float c  = warpRedMin(minC);
            float rh = warpRedMax(r127);
            float ch = warpRedMax(c127);
            if (lane == 0) {
                s.red[wid]          = g;
                s.red[NW + wid]     = r;
                s.red[2 * NW + wid] = c;
                s.red[3 * NW + wid] = rh;
                s.red[4 * NW + wid] = ch;
            }
        }
        __syncthreads();
        if (wid == 0) {
            float g  = (lane < NW) ? s.red[lane]          : -3.0e38f;
            float r  = (lane < NW) ? s.red[NW + lane]     :  3.0e38f;
            float c  = (lane < NW) ? s.red[2 * NW + lane] :  3.0e38f;
            float rh = (lane < NW) ? s.red[3 * NW + lane] : -3.0e38f;
            float ch = (lane < NW) ? s.red[4 * NW + lane] : -3.0e38f;
            g = warpRedMax(g); r = warpRedMin(r); c = warpRedMin(c);
            rh = warpRedMax(rh); ch = warpRedMax(ch);
            if (lane == 0) {
                float thr = 0.1f * g;
                s.thr  = thr;
                s.lo_r = (r >= thr) ? 1.0f : 0.0f;
                s.lo_c = (c >= thr) ? 1.0f : 0.0f;
                s.fastflag = (r < thr) && (c < thr) && (rh >= thr) && (ch >= thr);
            }
        }
        __syncthreads();

        float* ob = out + (size_t)img * (OH * OW);

        if (s.fastflag) {
            // ==== Fast path: column resize in registers, direct stores ====
            const float w0 = (lane == 0)  ? 0.0f : WI0;
            const float w1 = (lane == 0)  ? CE0  : WI1;
            const float w2 = (lane == 0)  ? CE0  : WI1;
            const float w3 = (lane == 0)  ? CE1  : WI0;
            const float u0 = (lane == 31) ? CE1  : WI0;
            const float u1 = (lane == 31) ? CE0  : WI1;
            const float u2 = (lane == 31) ? CE0  : WI1;
            const float u3 = (lane == 31) ? 0.0f : WI0;
            #pragma unroll
            for (int t = 0; t < 2; t++) {
                const int p = wid + NW * t;
                {
                    float lA = __shfl_up_sync(0xffffffffu, accA[t].w, 1);
                    float rA = __shfl_down_sync(0xffffffffu, accA[t].x, 1);
                    float o0 = fmaf(w0, lA, fmaf(w1, accA[t].x, fmaf(w2, accA[t].y, w3 * accA[t].z)));
                    float o1 = fmaf(u0, accA[t].y, fmaf(u1, accA[t].z, fmaf(u2, accA[t].w, u3 * rA)));
                    reinterpret_cast<float2*>(ob + (2 * p) * OW)[lane] = make_float2(o0, o1);
                }
                {
                    float lB = __shfl_up_sync(0xffffffffu, accB[t].w, 1);
                    float rB = __shfl_down_sync(0xffffffffu, accB[t].x, 1);
                    float o0 = fmaf(w0, lB, fmaf(w1, accB[t].x, fmaf(w2, accB[t].y, w3 * accB[t].z)));
                    float o1 = fmaf(u0, accB[t].y, fmaf(u1, accB[t].z, fmaf(u2, accB[t].w, u3 * rB)));
                    reinterpret_cast<float2*>(ob + (2 * p + 1) * OW)[lane] = make_float2(o0, o1);
                }
            }
        } else {
            // ==== Generic path (rare): exact hi_r/hi_c, weights, striped resize ====
            const float thr = s.thr;
            {
                float candR = 0.0f, candC = 0.0f;
                #pragma unroll
                for (int t = 0; t < 2; t++) {
                    #pragma unroll
                    for (int j = 0; j < 4; j++) {
                        int rr = 4 * (wid + NW * t) + j;     // owned row
                        if (rr >= 1 && m4v[t][j] >= thr) candR = fmaxf(candR, (float)rr);
                    }
                }
                const float base = (float)(4 * lane);
                if (lane > 0 && cmax.x >= thr) candC = fmaxf(candC, base);
                if (cmax.y >= thr) candC = fmaxf(candC, base + 1.0f);
                if (cmax.z >= thr) candC = fmaxf(candC, base + 2.0f);
                if (cmax.w >= thr) candC = fmaxf(candC, base + 3.0f);
                candR = warpRedMax(candR);
                candC = warpRedMax(candC);
                if (lane == 0) { s.red[wid] = candR; s.red[NW + wid] = candC; }
            }
            __syncthreads();
            if (wid == 0) {
                float hr = (lane < NW) ? s.red[lane]      : 0.0f;
                float hc = (lane < NW) ? s.red[NW + lane] : 0.0f;
                hr = warpRedMax(hr); hc = warpRedMax(hc);
                if (lane == 0) { s.hi_r = hr; s.hi_c = hc; }
            }
            __syncthreads();

            if (tid < OH + OW) {
                const bool isRow = tid < OH;
                const int  o  = isRow ? tid : tid - OH;
                const float lo = isRow ? s.lo_r : s.lo_c;
                const float hi = isRow ? s.hi_r : s.hi_c;
                const float L       = hi - lo + 1.0f;
                const float scale   = L / 64.0f;
                const float support = fmaxf(scale, 1.0f);
                const float center  = scale * ((float)o + 0.5f);
                const float base    = (lo - 0.5f) + center;
                float a0f = fminf(fmaxf(base - support, -8.0f), 160.0f);
                int j0 = (int)ceilf(a0f);
                float wv[TAPS];
                float ssum = 0.0f;
                #pragma unroll
                for (int a = 0; a < TAPS; a++) {
                    float jf  = (float)(j0 + a);
                    float pos = (jf - lo) + 0.5f;
                    float tt  = (pos - center) / support;
                    float wt  = fmaxf(0.0f, 1.0f - fabsf(tt));
                    if (!(jf >= lo && jf <= hi)) wt = 0.0f;
                    wv[a] = wt;
                    ssum += wt;
                }
                float denom = fmaxf(ssum, 1e-12f);
                if (isRow) {
                    s.jr[o] = j0;
                    #pragma unroll
                    for (int a = 0; a < TAPS; a++) s.wh[o][a] = wv[a] / denom;
                } else {
                    s.jc[o] = j0;
                    #pragma unroll
                    for (int a = 0; a < TAPS; a++) s.ww[o][a] = wv[a] / denom;
                }
            }
            __syncthreads();

            float4* tmp4 = reinterpret_cast<float4*>(s.scratch);
            #pragma unroll 1
            for (int st = 0; st < 4; st++) {          // 4 stripes of 16 rows
                {
                    int o  = st * NW + wid;
                    int j0 = s.jr[o];
                    const float* wrow = s.wh[o];
                    float4 acc = make_float4(0.f, 0.f, 0.f, 0.f);
                    #pragma unroll
                    for (int a = 0; a < TAPS; a++) {
                        int j = min(max(j0 + a, 0), H - 1);
                        float4 v = im4[j * (W / 4) + lane];
                        float wt = wrow[a];
                        acc.x = fmaf(wt, v.x, acc.x);
                        acc.y = fmaf(wt, v.y, acc.y);
                        acc.z = fmaf(wt, v.z, acc.z);
                        acc.w = fmaf(wt, v.w, acc.w);
                    }
                    tmp4[wid * (W / 4) + lane] = acc;
                }
                __syncthreads();
                #pragma unroll
                for (int it = 0; it < (NW * OW) / NT; it++) {
                    int i = tid + it * NT;
                    int ol = i >> 6;
                    int p  = i & 63;
                    int k0 = s.jc[p];
                    const float* wcol = s.ww[p];
                    const float* trow = s.scratch + ol * W;
                    float acc = 0.0f;
                    #pragma unroll
                    for (int b = 0; b < TAPS; b++) {
                        int kk = min(max(k0 + b, 0), W - 1);
                        acc = fmaf(wcol[b], trow[kk], acc);
                    }
                    ob[(st * NW + ol) * OW + p] = acc;
                }
                __syncthreads();
            }
        }
    }
}

} // anonymous namespace

extern "C" void kernel_launch(void* const* d_in, const int* in_sizes, int n_in,
                              void* d_out, int out_size) {
    const float* x = (const float*)d_in[0];
    float* out = (float*)d_out;
    const int nimg = in_sizes[0] / (H * W);   // N*C = 4096
    cudaFuncSetAttribute(smartpool_kernel,
                         cudaFuncAttributeMaxDynamicSharedMemorySize,
                         (int)sizeof(Smem));
    int grid = nimg < GRID ? nimg : GRID;
    smartpool_kernel<<<grid, NT, sizeof(Smem)>>>(x, out, nimg);
}